// round 2
// baseline (speedup 1.0000x reference)
#include <cuda_runtime.h>

// Problem constants (match reference)
#define NNODES 50000
#define DIN    128      // D
#define NH     128      // HIDDEN
#define PCOLS  256      // Pa(128) | Pb(128) per node

// Scratch: per-node projections. Pa = z@W1[:128] + b1, Pb = z@W1[128:]
// 50000 * 256 * 4B = 51.2 MB (fits in L2 for the edge kernel's gathers).
__device__ __align__(16) float g_P[(size_t)NNODES * PCOLS];

// Flag: 1 if edge index tensor is int64 on device, 0 if int32.
__device__ int g_e_is64;

// ---------------------------------------------------------------------------
// Kernel 0: detect whether e is int64 or int32 by inspecting the raw words.
// If int64 with values < 50000, every odd 32-bit word is 0. If int32, odd
// words are random node ids (probability all 64 are zero is ~(1/50000)^64).
// ---------------------------------------------------------------------------
__global__ void detect_e_dtype_kernel(const int* __restrict__ e32)
{
    int is64 = 1;
#pragma unroll 1
    for (int i = 0; i < 64; i++) {
        if (e32[2 * i + 1] != 0) { is64 = 0; break; }
    }
    g_e_is64 = is64;
}

// ---------------------------------------------------------------------------
// Kernel 1: node projection GEMM.  M=50000, N=256, K=128, fp32.
// Block tile 64(M) x 64(N), 256 threads (16x16), 4x4 micro-tile per thread.
// ---------------------------------------------------------------------------
__global__ __launch_bounds__(256) void node_proj_kernel(
    const float* __restrict__ z,
    const float* __restrict__ W1,
    const float* __restrict__ b1)
{
    const int m0 = blockIdx.x * 64;           // node tile base
    const int n0 = blockIdx.y * 64;           // output-column tile base (0,64,128,192)
    const int half = (n0 >= NH) ? 1 : 0;
    const float* Wbase = W1 + (size_t)half * NH * NH + (n0 - half * NH);

    __shared__ __align__(16) float As[16][68];   // As[k][m]
    __shared__ __align__(16) float Bs[16][68];   // Bs[k][n]

    const int t  = threadIdx.x;
    const int tx = t & 15;         // n direction
    const int ty = t >> 4;         // m direction

    float acc[4][4];
#pragma unroll
    for (int r = 0; r < 4; r++)
#pragma unroll
        for (int c = 0; c < 4; c++) acc[r][c] = 0.f;

    // A-load mapping: thread -> (row m, 4 consecutive k)
    const int a_m  = t >> 2;          // 0..63
    const int a_kq = (t & 3) * 4;     // 0,4,8,12
    int a_row = m0 + a_m;
    if (a_row >= NNODES) a_row = NNODES - 1;   // clamp (stores are guarded)

    // B-load mapping: thread -> (k, 4 consecutive n)
    const int b_k  = t >> 4;          // 0..15
    const int b_n4 = (t & 15) * 4;    // 0..60

#pragma unroll 1
    for (int k0 = 0; k0 < DIN; k0 += 16) {
        // load A tile (transposed into As[k][m])
        float4 av = *reinterpret_cast<const float4*>(z + (size_t)a_row * DIN + k0 + a_kq);
        As[a_kq + 0][a_m] = av.x;
        As[a_kq + 1][a_m] = av.y;
        As[a_kq + 2][a_m] = av.z;
        As[a_kq + 3][a_m] = av.w;
        // load B tile
        float4 bv = *reinterpret_cast<const float4*>(Wbase + (size_t)(k0 + b_k) * NH + b_n4);
        *reinterpret_cast<float4*>(&Bs[b_k][b_n4]) = bv;
        __syncthreads();

#pragma unroll
        for (int k = 0; k < 16; k++) {
            float4 a4 = *reinterpret_cast<const float4*>(&As[k][ty * 4]);
            float4 b4 = *reinterpret_cast<const float4*>(&Bs[k][tx * 4]);
            float ar[4] = {a4.x, a4.y, a4.z, a4.w};
            float br[4] = {b4.x, b4.y, b4.z, b4.w};
#pragma unroll
            for (int r = 0; r < 4; r++)
#pragma unroll
                for (int c = 0; c < 4; c++)
                    acc[r][c] = fmaf(ar[r], br[c], acc[r][c]);
        }
        __syncthreads();
    }

    // epilogue: add b1 to Pa half, store
    float4 bias;
    if (half == 0) {
        bias = *reinterpret_cast<const float4*>(b1 + n0 + tx * 4);
    } else {
        bias.x = bias.y = bias.z = bias.w = 0.f;
    }
#pragma unroll
    for (int r = 0; r < 4; r++) {
        int row = m0 + ty * 4 + r;
        if (row < NNODES) {
            float4 v;
            v.x = acc[r][0] + bias.x;
            v.y = acc[r][1] + bias.y;
            v.z = acc[r][2] + bias.z;
            v.w = acc[r][3] + bias.w;
            *reinterpret_cast<float4*>(g_P + (size_t)row * PCOLS + n0 + tx * 4) = v;
        }
    }
}

// ---------------------------------------------------------------------------
// Kernel 2: edge kernel. One warp per edge.
// Gather Pa[src] (512B) + Pb[dst] (512B), relu-add, dot with w2, sigmoid.
// ---------------------------------------------------------------------------
__global__ __launch_bounds__(256) void edge_kernel(
    const int* __restrict__ e32,
    const float* __restrict__ W2,
    const float* __restrict__ b2,
    float* __restrict__ out,
    int E)
{
    const int lane = threadIdx.x & 31;
    const int i = (int)((blockIdx.x * (unsigned)blockDim.x + threadIdx.x) >> 5);
    if (i >= E) return;

    const float4 w2v = *reinterpret_cast<const float4*>(W2 + lane * 4);

    int src, dst;
    if (g_e_is64) {
        // int64 storage: value lives in the low 32-bit word of each element
        src = __ldg(e32 + 2 * (size_t)i);
        dst = __ldg(e32 + 2 * ((size_t)E + i));
    } else {
        src = __ldg(e32 + i);
        dst = __ldg(e32 + E + i);
    }
    // defensive clamp: wrong answer beats illegal access for diagnosability
    src = min(max(src, 0), NNODES - 1);
    dst = min(max(dst, 0), NNODES - 1);

    const float4 pa = *reinterpret_cast<const float4*>(g_P + (size_t)src * PCOLS + lane * 4);
    const float4 pb = *reinterpret_cast<const float4*>(g_P + (size_t)dst * PCOLS + NH + lane * 4);

    float hx = fmaxf(pa.x + pb.x, 0.f);
    float hy = fmaxf(pa.y + pb.y, 0.f);
    float hz = fmaxf(pa.z + pb.z, 0.f);
    float hw = fmaxf(pa.w + pb.w, 0.f);

    float acc = hx * w2v.x + hy * w2v.y + hz * w2v.z + hw * w2v.w;
#pragma unroll
    for (int off = 16; off > 0; off >>= 1)
        acc += __shfl_xor_sync(0xFFFFFFFFu, acc, off);

    if (lane == 0) {
        float u = acc + __ldg(b2);
        out[i] = 1.f / (1.f + __expf(-u));
    }
}

// ---------------------------------------------------------------------------
// Launch
// Inputs (metadata order): z[50000*128] f32, e[2*600000] (i64 or i32),
//                          W1[256*128] f32, b1[128] f32, W2[128] f32, b2[1] f32.
// out: [E] f32.
// ---------------------------------------------------------------------------
extern "C" void kernel_launch(void* const* d_in, const int* in_sizes, int n_in,
                              void* d_out, int out_size)
{
    const float* z   = (const float*)d_in[0];
    const int*   e32 = (const int*)d_in[1];
    const float* W1  = (const float*)d_in[2];
    const float* b1  = (const float*)d_in[3];
    const float* W2  = (const float*)d_in[4];
    const float* b2  = (const float*)d_in[5];
    float*       out = (float*)d_out;

    const int E = in_sizes[1] / 2;

    detect_e_dtype_kernel<<<1, 1>>>(e32);

    dim3 grid1((NNODES + 63) / 64, PCOLS / 64);
    node_proj_kernel<<<grid1, 256>>>(z, W1, b1);

    const int warps_per_block = 256 / 32;
    int blocks2 = (E + warps_per_block - 1) / warps_per_block;
    edge_kernel<<<blocks2, 256>>>(e32, W2, b2, out, E);
}

// round 8
// speedup vs baseline: 1.1717x; 1.1717x over previous
#include <cuda_runtime.h>
#include <cuda_fp16.h>

// Problem constants (match reference)
#define NNODES 50000
#define DIN    128      // D
#define NH     128      // HIDDEN
#define PCOLS  256      // Pa(128) | Pb(128) per node

// Scratch: per-node projections in fp16. Pa = z@W1[:128] + b1, Pb = z@W1[128:]
// 50000 * 256 * 2B = 25.6 MB -> fully L2-resident for the edge gathers.
__device__ __align__(16) __half g_Ph[(size_t)NNODES * PCOLS];

// Flag: 1 if edge index tensor is int64 on device, 0 if int32.
__device__ int g_e_is64;

// ---------------------------------------------------------------------------
// Kernel 0: detect int64 vs int32 edge indices. If int64 with values < 50000,
// every odd 32-bit word is 0. 64 lanes check one word each + ballot.
// ---------------------------------------------------------------------------
__global__ void detect_e_dtype_kernel(const int* __restrict__ e32)
{
    const int t = threadIdx.x;                 // 0..63
    int nz = (e32[2 * t + 1] != 0) ? 1 : 0;
    unsigned b = __ballot_sync(0xFFFFFFFFu, nz);
    __shared__ int s_nz[2];
    if ((t & 31) == 0) s_nz[t >> 5] = (b != 0);
    __syncthreads();
    if (t == 0) g_e_is64 = (s_nz[0] | s_nz[1]) ? 0 : 1;
}

// ---------------------------------------------------------------------------
// Kernel 1: node projection GEMM. M=50000, N=128 per half, K=128, fp32 math,
// fp16 output. Block tile 128x128, 256 threads, 8x8 micro-tile (1:1 FMA:LDS).
// grid = (ceil(M/128), 2); blockIdx.y selects Pa/Pb half.
// ---------------------------------------------------------------------------
__global__ __launch_bounds__(256) void node_proj_kernel(
    const float* __restrict__ z,
    const float* __restrict__ W1,
    const float* __restrict__ b1)
{
    const int m0   = blockIdx.x * 128;
    const int half = blockIdx.y;               // 0 -> Pa (+b1), 1 -> Pb
    const float* Wbase = W1 + (size_t)half * NH * NH;

    __shared__ __align__(16) float As[16][128]; // As[k][m]
    __shared__ __align__(16) float Bs[16][128]; // Bs[k][n]

    const int t  = threadIdx.x;
    const int tx = t & 15;          // n dir: 8 cols each
    const int ty = t >> 4;          // m dir: 8 rows each

    float acc[8][8];
#pragma unroll
    for (int r = 0; r < 8; r++)
#pragma unroll
        for (int c = 0; c < 8; c++) acc[r][c] = 0.f;

    // A-load: thread t covers row (t>>1), k window (t&1)*8 .. +8 (2 float4)
    const int a_m  = t >> 1;
    const int a_k8 = (t & 1) * 8;
    int a_row = m0 + a_m;
    if (a_row >= NNODES) a_row = NNODES - 1;    // clamp; stores guarded

    // B-load: thread t covers k row (t>>4), n window (t&15)*8 .. +8
    const int b_k  = t >> 4;
    const int b_n8 = (t & 15) * 8;

#pragma unroll 1
    for (int k0 = 0; k0 < DIN; k0 += 16) {
        // A tile, transposed into As[k][m]
        float4 a0 = *reinterpret_cast<const float4*>(z + (size_t)a_row * DIN + k0 + a_k8);
        float4 a1 = *reinterpret_cast<const float4*>(z + (size_t)a_row * DIN + k0 + a_k8 + 4);
        As[a_k8 + 0][a_m] = a0.x; As[a_k8 + 1][a_m] = a0.y;
        As[a_k8 + 2][a_m] = a0.z; As[a_k8 + 3][a_m] = a0.w;
        As[a_k8 + 4][a_m] = a1.x; As[a_k8 + 5][a_m] = a1.y;
        As[a_k8 + 6][a_m] = a1.z; As[a_k8 + 7][a_m] = a1.w;
        // B tile
        float4 w0 = *reinterpret_cast<const float4*>(Wbase + (size_t)(k0 + b_k) * NH + b_n8);
        float4 w1 = *reinterpret_cast<const float4*>(Wbase + (size_t)(k0 + b_k) * NH + b_n8 + 4);
        *reinterpret_cast<float4*>(&Bs[b_k][b_n8])     = w0;
        *reinterpret_cast<float4*>(&Bs[b_k][b_n8 + 4]) = w1;
        __syncthreads();

#pragma unroll
        for (int k = 0; k < 16; k++) {
            float4 av0 = *reinterpret_cast<const float4*>(&As[k][ty * 8]);
            float4 av1 = *reinterpret_cast<const float4*>(&As[k][ty * 8 + 4]);
            float4 bv0 = *reinterpret_cast<const float4*>(&Bs[k][tx * 8]);
            float4 bv1 = *reinterpret_cast<const float4*>(&Bs[k][tx * 8 + 4]);
            float ar[8] = {av0.x, av0.y, av0.z, av0.w, av1.x, av1.y, av1.z, av1.w};
            float br[8] = {bv0.x, bv0.y, bv0.z, bv0.w, bv1.x, bv1.y, bv1.z, bv1.w};
#pragma unroll
            for (int r = 0; r < 8; r++)
#pragma unroll
                for (int c = 0; c < 8; c++)
                    acc[r][c] = fmaf(ar[r], br[c], acc[r][c]);
        }
        __syncthreads();
    }

    // epilogue: +b1 for Pa half, convert to fp16, store 16B per row
    float bias[8];
    if (half == 0) {
        float4 t0 = *reinterpret_cast<const float4*>(b1 + tx * 8);
        float4 t1 = *reinterpret_cast<const float4*>(b1 + tx * 8 + 4);
        bias[0]=t0.x; bias[1]=t0.y; bias[2]=t0.z; bias[3]=t0.w;
        bias[4]=t1.x; bias[5]=t1.y; bias[6]=t1.z; bias[7]=t1.w;
    } else {
#pragma unroll
        for (int c = 0; c < 8; c++) bias[c] = 0.f;
    }
#pragma unroll
    for (int r = 0; r < 8; r++) {
        int row = m0 + ty * 8 + r;
        if (row < NNODES) {
            __half hv[8];
#pragma unroll
            for (int c = 0; c < 8; c++) hv[c] = __float2half_rn(acc[r][c] + bias[c]);
            *reinterpret_cast<uint4*>(g_Ph + (size_t)row * PCOLS + half * NH + tx * 8) =
                *reinterpret_cast<const uint4*>(hv);
        }
    }
}

// ---------------------------------------------------------------------------
// Kernel 2: edge kernel. One warp per edge.
// Gather fp16 Pa[src] (256B) + Pb[dst] (256B), relu-add in fp32, dot w2, sigmoid.
// ---------------------------------------------------------------------------
__global__ __launch_bounds__(256) void edge_kernel(
    const int* __restrict__ e32,
    const float* __restrict__ W2,
    const float* __restrict__ b2,
    float* __restrict__ out,
    int E)
{
    const int lane = threadIdx.x & 31;
    const int i = (int)((blockIdx.x * (unsigned)blockDim.x + threadIdx.x) >> 5);
    if (i >= E) return;

    const float4 w2v = *reinterpret_cast<const float4*>(W2 + lane * 4);

    int src, dst;
    if (g_e_is64) {
        src = __ldg(e32 + 2 * (size_t)i);
        dst = __ldg(e32 + 2 * ((size_t)E + i));
    } else {
        src = __ldg(e32 + i);
        dst = __ldg(e32 + E + i);
    }
    src = min(max(src, 0), NNODES - 1);
    dst = min(max(dst, 0), NNODES - 1);

    // 4 halves per lane from each table half (8B loads)
    const __half2* pa = reinterpret_cast<const __half2*>(g_Ph + (size_t)src * PCOLS + lane * 4);
    const __half2* pb = reinterpret_cast<const __half2*>(g_Ph + (size_t)dst * PCOLS + NH + lane * 4);
    __half2 pa01 = pa[0], pa23 = pa[1];
    __half2 pb01 = pb[0], pb23 = pb[1];

    float2 a01 = __half22float2(pa01), a23 = __half22float2(pa23);
    float2 c01 = __half22float2(pb01), c23 = __half22float2(pb23);

    float h0 = fmaxf(a01.x + c01.x, 0.f);
    float h1 = fmaxf(a01.y + c01.y, 0.f);
    float h2 = fmaxf(a23.x + c23.x, 0.f);
    float h3 = fmaxf(a23.y + c23.y, 0.f);

    float acc = h0 * w2v.x + h1 * w2v.y + h2 * w2v.z + h3 * w2v.w;
#pragma unroll
    for (int off = 16; off > 0; off >>= 1)
        acc += __shfl_xor_sync(0xFFFFFFFFu, acc, off);

    if (lane == 0) {
        float u = acc + __ldg(b2);
        out[i] = 1.f / (1.f + __expf(-u));
    }
}

// ---------------------------------------------------------------------------
// Launch
// ---------------------------------------------------------------------------
extern "C" void kernel_launch(void* const* d_in, const int* in_sizes, int n_in,
                              void* d_out, int out_size)
{
    const float* z   = (const float*)d_in[0];
    const int*   e32 = (const int*)d_in[1];
    const float* W1  = (const float*)d_in[2];
    const float* b1  = (const float*)d_in[3];
    const float* W2  = (const float*)d_in[4];
    const float* b2  = (const float*)d_in[5];
    float*       out = (float*)d_out;

    const int E = in_sizes[1] / 2;

    detect_e_dtype_kernel<<<1, 64>>>(e32);

    dim3 grid1((NNODES + 127) / 128, 2);
    node_proj_kernel<<<grid1, 256>>>(z, W1, b1);

    const int warps_per_block = 256 / 32;
    int blocks2 = (E + warps_per_block - 1) / warps_per_block;
    edge_kernel<<<blocks2, 256>>>(e32, W2, b2, out, E);
}

// round 11
// speedup vs baseline: 1.5057x; 1.2851x over previous
#include <cuda_runtime.h>
#include <cuda_fp16.h>

// Problem constants
#define NNODES 50000
#define DIN    128
#define NH     128
#define PCOLS  256

// fp16 projection table: Pa = z@W1[:128]+b1 | Pb = z@W1[128:]. 25.6 MB, L2-resident.
__device__ __align__(16) __half g_Ph[(size_t)NNODES * PCOLS];
__device__ int g_e_is64;

// ---------------------------------------------------------------------------
// tf32 helpers
// ---------------------------------------------------------------------------
__device__ __forceinline__ unsigned f2tf32(float x) {
    unsigned r;
    asm("cvt.rna.tf32.f32 %0, %1;" : "=r"(r) : "f"(x));
    return r;
}

__device__ __forceinline__ void mma_tf32(float c[4], const unsigned a[4], const unsigned b[2]) {
    asm volatile(
        "mma.sync.aligned.m16n8k8.row.col.f32.tf32.tf32.f32 "
        "{%0,%1,%2,%3}, {%4,%5,%6,%7}, {%8,%9}, {%0,%1,%2,%3};\n"
        : "+f"(c[0]), "+f"(c[1]), "+f"(c[2]), "+f"(c[3])
        : "r"(a[0]), "r"(a[1]), "r"(a[2]), "r"(a[3]), "r"(b[0]), "r"(b[1]));
}

// ---------------------------------------------------------------------------
// Kernel 1: node projection GEMM on tensor cores (tf32).
// C[128 tile, 128] = z_tile[128,128] @ W1_half[128,128], fp32 accum, fp16 out.
// 256 threads = 8 warps; warp tile 64(M)x32(N); m16n8k8 fragments.
// grid = (ceil(M/128), 2 halves). Block (0,0) also detects e's dtype.
// ---------------------------------------------------------------------------
#define AS_STRIDE 36    // 128 x 32 A tile, padded: bank = (4g+c) conflict-free frag reads
#define BS_STRIDE 132   // 32 x 128 B tile, padded likewise

__global__ __launch_bounds__(256, 2) void node_proj_tc_kernel(
    const float* __restrict__ z,
    const float* __restrict__ W1,
    const float* __restrict__ b1,
    const int*   __restrict__ e32)
{
    // Fold int64/int32 detection into one warp of one block (saves a launch).
    if (blockIdx.x == 0 && blockIdx.y == 0 && threadIdx.x < 32) {
        int l = threadIdx.x;
        int nz = (e32[2 * (2 * l) + 1] != 0) | (e32[2 * (2 * l + 1) + 1] != 0);
        unsigned bb = __ballot_sync(0xFFFFFFFFu, nz);
        if (l == 0) g_e_is64 = (bb == 0) ? 1 : 0;
    }

    __shared__ unsigned As[128 * AS_STRIDE];
    __shared__ unsigned Bs[32 * BS_STRIDE];

    const int m0   = blockIdx.x * 128;
    const int half = blockIdx.y;                    // 0 -> Pa(+b1), 1 -> Pb
    const float* Wbase = W1 + (size_t)half * NH * NH;

    const int t    = threadIdx.x;
    const int lane = t & 31;
    const int wid  = t >> 5;
    const int wm   = wid >> 2;                      // 0..1 -> m offset 64*wm
    const int wn   = wid & 3;                       // 0..3 -> n offset 32*wn
    const int g    = lane >> 2;                     // 0..7
    const int c    = lane & 3;                      // 0..3

    float acc[4][4][4];
#pragma unroll
    for (int ms = 0; ms < 4; ms++)
#pragma unroll
        for (int ns = 0; ns < 4; ns++)
#pragma unroll
            for (int r = 0; r < 4; r++) acc[ms][ns][r] = 0.f;

    // gmem->smem mapping: A: 128 rows x 32 k, 2 threads/row x 16 floats
    const int arow  = t >> 1;
    const int acol0 = (t & 1) * 16;
    int a_row_g = m0 + arow;
    if (a_row_g >= NNODES) a_row_g = NNODES - 1;    // clamp; stores guarded
    // B: 32 k-rows x 128 n, 8 threads/row x 16 floats
    const int brow  = t >> 3;
    const int bcol0 = (t & 7) * 16;

#pragma unroll 1
    for (int k0 = 0; k0 < DIN; k0 += 32) {
        // ---- load + convert to tf32 in smem ----
        const float* zsrc = z + (size_t)a_row_g * DIN + k0 + acol0;
        unsigned* adst = &As[arow * AS_STRIDE + acol0];
#pragma unroll
        for (int j = 0; j < 4; j++) {
            float4 v = *reinterpret_cast<const float4*>(zsrc + 4 * j);
            adst[4*j+0] = f2tf32(v.x); adst[4*j+1] = f2tf32(v.y);
            adst[4*j+2] = f2tf32(v.z); adst[4*j+3] = f2tf32(v.w);
        }
        const float* wsrc = Wbase + (size_t)(k0 + brow) * NH + bcol0;
        unsigned* bdst = &Bs[brow * BS_STRIDE + bcol0];
#pragma unroll
        for (int j = 0; j < 4; j++) {
            float4 v = *reinterpret_cast<const float4*>(wsrc + 4 * j);
            bdst[4*j+0] = f2tf32(v.x); bdst[4*j+1] = f2tf32(v.y);
            bdst[4*j+2] = f2tf32(v.z); bdst[4*j+3] = f2tf32(v.w);
        }
        __syncthreads();

        // ---- 4 k-chunks of 8 ----
#pragma unroll
        for (int ko = 0; ko < 4; ko++) {
            const int kb = ko * 8;
            unsigned a[4][4], b[4][2];
#pragma unroll
            for (int ms = 0; ms < 4; ms++) {
                const int r0 = wm * 64 + ms * 16 + g;
                a[ms][0] = As[ r0      * AS_STRIDE + kb + c    ];
                a[ms][1] = As[(r0 + 8) * AS_STRIDE + kb + c    ];
                a[ms][2] = As[ r0      * AS_STRIDE + kb + c + 4];
                a[ms][3] = As[(r0 + 8) * AS_STRIDE + kb + c + 4];
            }
#pragma unroll
            for (int ns = 0; ns < 4; ns++) {
                const int col = wn * 32 + ns * 8 + g;
                b[ns][0] = Bs[(kb + c    ) * BS_STRIDE + col];
                b[ns][1] = Bs[(kb + c + 4) * BS_STRIDE + col];
            }
#pragma unroll
            for (int ms = 0; ms < 4; ms++)
#pragma unroll
                for (int ns = 0; ns < 4; ns++)
                    mma_tf32(acc[ms][ns], a[ms], b[ns]);
        }
        __syncthreads();
    }

    // ---- epilogue: +bias (half 0), fp16 pack, store ----
#pragma unroll
    for (int ms = 0; ms < 4; ms++) {
        const int r0 = m0 + wm * 64 + ms * 16 + g;
#pragma unroll
        for (int ns = 0; ns < 4; ns++) {
            const int col = wn * 32 + ns * 8 + 2 * c;   // within-half column
            float bx = 0.f, by = 0.f;
            if (half == 0) { bx = __ldg(b1 + col); by = __ldg(b1 + col + 1); }
            if (r0 < NNODES) {
                __half2 h = __floats2half2_rn(acc[ms][ns][0] + bx, acc[ms][ns][1] + by);
                *reinterpret_cast<__half2*>(g_Ph + (size_t)r0 * PCOLS + half * NH + col) = h;
            }
            if (r0 + 8 < NNODES) {
                __half2 h = __floats2half2_rn(acc[ms][ns][2] + bx, acc[ms][ns][3] + by);
                *reinterpret_cast<__half2*>(g_Ph + (size_t)(r0 + 8) * PCOLS + half * NH + col) = h;
            }
        }
    }
}

// ---------------------------------------------------------------------------
// Kernel 2: edge kernel. One warp per edge; 8B gather per lane per half.
// ---------------------------------------------------------------------------
__global__ __launch_bounds__(256) void edge_kernel(
    const int* __restrict__ e32,
    const float* __restrict__ W2,
    const float* __restrict__ b2,
    float* __restrict__ out,
    int E)
{
    const int lane = threadIdx.x & 31;
    const int i = (int)((blockIdx.x * (unsigned)blockDim.x + threadIdx.x) >> 5);
    if (i >= E) return;

    const float4 w2v = *reinterpret_cast<const float4*>(W2 + lane * 4);

    int src, dst;
    if (g_e_is64) {
        src = __ldg(e32 + 2 * (size_t)i);
        dst = __ldg(e32 + 2 * ((size_t)E + i));
    } else {
        src = __ldg(e32 + i);
        dst = __ldg(e32 + E + i);
    }
    src = min(max(src, 0), NNODES - 1);
    dst = min(max(dst, 0), NNODES - 1);

    const uint2 pa = *(reinterpret_cast<const uint2*>(g_Ph + (size_t)src * PCOLS) + lane);
    const uint2 pb = *(reinterpret_cast<const uint2*>(g_Ph + (size_t)dst * PCOLS + NH) + lane);

    float2 a01 = __half22float2(*reinterpret_cast<const __half2*>(&pa.x));
    float2 a23 = __half22float2(*reinterpret_cast<const __half2*>(&pa.y));
    float2 c01 = __half22float2(*reinterpret_cast<const __half2*>(&pb.x));
    float2 c23 = __half22float2(*reinterpret_cast<const __half2*>(&pb.y));

    float h0 = fmaxf(a01.x + c01.x, 0.f);
    float h1 = fmaxf(a01.y + c01.y, 0.f);
    float h2 = fmaxf(a23.x + c23.x, 0.f);
    float h3 = fmaxf(a23.y + c23.y, 0.f);

    float acc = h0 * w2v.x + h1 * w2v.y + h2 * w2v.z + h3 * w2v.w;
#pragma unroll
    for (int off = 16; off > 0; off >>= 1)
        acc += __shfl_xor_sync(0xFFFFFFFFu, acc, off);

    if (lane == 0) {
        float u = acc + __ldg(b2);
        out[i] = 1.f / (1.f + __expf(-u));
    }
}

// ---------------------------------------------------------------------------
// Launch
// ---------------------------------------------------------------------------
extern "C" void kernel_launch(void* const* d_in, const int* in_sizes, int n_in,
                              void* d_out, int out_size)
{
    const float* z   = (const float*)d_in[0];
    const int*   e32 = (const int*)d_in[1];
    const float* W1  = (const float*)d_in[2];
    const float* b1  = (const float*)d_in[3];
    const float* W2  = (const float*)d_in[4];
    const float* b2  = (const float*)d_in[5];
    float*       out = (float*)d_out;

    const int E = in_sizes[1] / 2;

    dim3 grid1((NNODES + 127) / 128, 2);
    node_proj_tc_kernel<<<grid1, 256>>>(z, W1, b1, e32);

    const int warps_per_block = 256 / 32;
    int blocks2 = (E + warps_per_block - 1) / warps_per_block;
    edge_kernel<<<blocks2, 256>>>(e32, W2, b2, out, E);
}

// round 12
// speedup vs baseline: 1.6925x; 1.1240x over previous
#include <cuda_runtime.h>
#include <cuda_fp16.h>

// Problem constants
#define NNODES 50000
#define DIN    128
#define NH     128
#define PCOLS  256

// fp16 projection table: Pa = z@W1[:128]+b1 | Pb = z@W1[128:]. 25.6 MB, L2-resident.
__device__ __align__(16) __half g_Ph[(size_t)NNODES * PCOLS];
__device__ int g_e_is64;

// ---------------------------------------------------------------------------
// tf32 mma (m16n8k8). Inputs are raw f32 bits; HW truncates to tf32.
// ---------------------------------------------------------------------------
__device__ __forceinline__ void mma_tf32(float c[4], const unsigned a[4], const unsigned b[2]) {
    asm volatile(
        "mma.sync.aligned.m16n8k8.row.col.f32.tf32.tf32.f32 "
        "{%0,%1,%2,%3}, {%4,%5,%6,%7}, {%8,%9}, {%0,%1,%2,%3};\n"
        : "+f"(c[0]), "+f"(c[1]), "+f"(c[2]), "+f"(c[3])
        : "r"(a[0]), "r"(a[1]), "r"(a[2]), "r"(a[3]), "r"(b[0]), "r"(b[1]));
}

// ---------------------------------------------------------------------------
// Kernel 1: node projection GEMM on tensor cores (tf32, truncated inputs).
// C[128,128] = z_tile @ W1_half; fp32 accum; fp16 out.
// 256 threads = 8 warps; warp tile 64x32; grid (ceil(M/128), 2).
// Block (0,0) warp 0 also detects e's dtype (saves a launch).
// ---------------------------------------------------------------------------
#define AS_STRIDE 36
#define BS_STRIDE 132

__global__ __launch_bounds__(256, 2) void node_proj_tc_kernel(
    const float* __restrict__ z,
    const float* __restrict__ W1,
    const float* __restrict__ b1,
    const int*   __restrict__ e32)
{
    if (blockIdx.x == 0 && blockIdx.y == 0 && threadIdx.x < 32) {
        int l = threadIdx.x;
        int nz = (e32[2 * (2 * l) + 1] != 0) | (e32[2 * (2 * l + 1) + 1] != 0);
        unsigned bb = __ballot_sync(0xFFFFFFFFu, nz);
        if (l == 0) g_e_is64 = (bb == 0) ? 1 : 0;
    }

    __shared__ unsigned As[128 * AS_STRIDE];
    __shared__ unsigned Bs[32 * BS_STRIDE];

    const int m0   = blockIdx.x * 128;
    const int half = blockIdx.y;                    // 0 -> Pa(+b1), 1 -> Pb
    const float* Wbase = W1 + (size_t)half * NH * NH;

    const int t    = threadIdx.x;
    const int lane = t & 31;
    const int wid  = t >> 5;
    const int wm   = wid >> 2;
    const int wn   = wid & 3;
    const int g    = lane >> 2;
    const int c    = lane & 3;

    float acc[4][4][4];
#pragma unroll
    for (int ms = 0; ms < 4; ms++)
#pragma unroll
        for (int ns = 0; ns < 4; ns++)
#pragma unroll
            for (int r = 0; r < 4; r++) acc[ms][ns][r] = 0.f;

    const int arow  = t >> 1;
    const int acol0 = (t & 1) * 16;
    int a_row_g = m0 + arow;
    if (a_row_g >= NNODES) a_row_g = NNODES - 1;
    const int brow  = t >> 3;
    const int bcol0 = (t & 7) * 16;

#pragma unroll 1
    for (int k0 = 0; k0 < DIN; k0 += 32) {
        // stage raw f32 bits (tf32 truncation happens in the MMA)
        const float* zsrc = z + (size_t)a_row_g * DIN + k0 + acol0;
        unsigned* adst = &As[arow * AS_STRIDE + acol0];
#pragma unroll
        for (int j = 0; j < 4; j++) {
            uint4 v = *reinterpret_cast<const uint4*>(zsrc + 4 * j);
            adst[4*j+0] = v.x; adst[4*j+1] = v.y; adst[4*j+2] = v.z; adst[4*j+3] = v.w;
        }
        const float* wsrc = Wbase + (size_t)(k0 + brow) * NH + bcol0;
        unsigned* bdst = &Bs[brow * BS_STRIDE + bcol0];
#pragma unroll
        for (int j = 0; j < 4; j++) {
            uint4 v = *reinterpret_cast<const uint4*>(wsrc + 4 * j);
            bdst[4*j+0] = v.x; bdst[4*j+1] = v.y; bdst[4*j+2] = v.z; bdst[4*j+3] = v.w;
        }
        __syncthreads();

#pragma unroll
        for (int ko = 0; ko < 4; ko++) {
            const int kb = ko * 8;
            unsigned a[4][4], b[4][2];
#pragma unroll
            for (int ms = 0; ms < 4; ms++) {
                const int r0 = wm * 64 + ms * 16 + g;
                a[ms][0] = As[ r0      * AS_STRIDE + kb + c    ];
                a[ms][1] = As[(r0 + 8) * AS_STRIDE + kb + c    ];
                a[ms][2] = As[ r0      * AS_STRIDE + kb + c + 4];
                a[ms][3] = As[(r0 + 8) * AS_STRIDE + kb + c + 4];
            }
#pragma unroll
            for (int ns = 0; ns < 4; ns++) {
                const int col = wn * 32 + ns * 8 + g;
                b[ns][0] = Bs[(kb + c    ) * BS_STRIDE + col];
                b[ns][1] = Bs[(kb + c + 4) * BS_STRIDE + col];
            }
#pragma unroll
            for (int ms = 0; ms < 4; ms++)
#pragma unroll
                for (int ns = 0; ns < 4; ns++)
                    mma_tf32(acc[ms][ns], a[ms], b[ns]);
        }
        __syncthreads();
    }

#pragma unroll
    for (int ms = 0; ms < 4; ms++) {
        const int r0 = m0 + wm * 64 + ms * 16 + g;
#pragma unroll
        for (int ns = 0; ns < 4; ns++) {
            const int col = wn * 32 + ns * 8 + 2 * c;
            float bx = 0.f, by = 0.f;
            if (half == 0) { bx = __ldg(b1 + col); by = __ldg(b1 + col + 1); }
            if (r0 < NNODES) {
                __half2 h = __floats2half2_rn(acc[ms][ns][0] + bx, acc[ms][ns][1] + by);
                *reinterpret_cast<__half2*>(g_Ph + (size_t)r0 * PCOLS + half * NH + col) = h;
            }
            if (r0 + 8 < NNODES) {
                __half2 h = __floats2half2_rn(acc[ms][ns][2] + bx, acc[ms][ns][3] + by);
                *reinterpret_cast<__half2*>(g_Ph + (size_t)(r0 + 8) * PCOLS + half * NH + col) = h;
            }
        }
    }
}

// ---------------------------------------------------------------------------
// Kernel 2: edge kernel. FOUR edges per warp, 8 lanes per edge.
// Each lane: 32B of Pa[src] + 32B of Pb[dst] (2+2 LDG.128), half2 add+relu,
// fp32 dot with its 16 w2 values, 3-round width-8 shuffle reduce.
// ---------------------------------------------------------------------------
__global__ __launch_bounds__(256) void edge_kernel(
    const int* __restrict__ e32,
    const float* __restrict__ W2,
    const float* __restrict__ b2,
    float* __restrict__ out,
    int E)
{
    const int lane = threadIdx.x & 31;
    const int warp = (int)(blockIdx.x * (blockDim.x >> 5)) + (threadIdx.x >> 5);
    const int sub  = lane >> 3;      // edge slot within warp: 0..3
    const int j    = lane & 7;       // 16-value chunk: 0..7

    int i = warp * 4 + sub;
    const bool valid = (i < E);
    if (i >= E) i = E - 1;           // safe duplicate; store guarded

    int src, dst;
    if (g_e_is64) {
        src = __ldg(e32 + 2 * (size_t)i);
        dst = __ldg(e32 + 2 * ((size_t)E + i));
    } else {
        src = __ldg(e32 + i);
        dst = __ldg(e32 + E + i);
    }
    src = min(max(src, 0), NNODES - 1);
    dst = min(max(dst, 0), NNODES - 1);

    // 16 halves from each table half per lane
    const uint4* pap = reinterpret_cast<const uint4*>(g_Ph + (size_t)src * PCOLS + j * 16);
    const uint4* pbp = reinterpret_cast<const uint4*>(g_Ph + (size_t)dst * PCOLS + NH + j * 16);
    uint4 pa0 = pap[0], pa1 = pap[1];
    uint4 pb0 = pbp[0], pb1 = pbp[1];

    const __half2* a2 = reinterpret_cast<const __half2*>(&pa0);   // 4 half2
    const __half2* a3 = reinterpret_cast<const __half2*>(&pa1);
    const __half2* b2v = reinterpret_cast<const __half2*>(&pb0);
    const __half2* b3v = reinterpret_cast<const __half2*>(&pb1);

    const __half2 zero2 = __float2half2_rn(0.f);
    __half2 h[8];
#pragma unroll
    for (int q = 0; q < 4; q++) h[q]     = __hmax2(__hadd2(a2[q], b2v[q]), zero2);
#pragma unroll
    for (int q = 0; q < 4; q++) h[4 + q] = __hmax2(__hadd2(a3[q], b3v[q]), zero2);

    // w2 chunk for this lane: 16 floats
    const float4* wp = reinterpret_cast<const float4*>(W2) + j * 4;
    float acc = 0.f;
#pragma unroll
    for (int q = 0; q < 4; q++) {
        float4 w = __ldg(wp + q);
        float2 f0 = __half22float2(h[2 * q]);
        float2 f1 = __half22float2(h[2 * q + 1]);
        acc = fmaf(f0.x, w.x, acc);
        acc = fmaf(f0.y, w.y, acc);
        acc = fmaf(f1.x, w.z, acc);
        acc = fmaf(f1.y, w.w, acc);
    }

    // reduce within each 8-lane group
    acc += __shfl_xor_sync(0xFFFFFFFFu, acc, 4, 8);
    acc += __shfl_xor_sync(0xFFFFFFFFu, acc, 2, 8);
    acc += __shfl_xor_sync(0xFFFFFFFFu, acc, 1, 8);

    if (j == 0 && valid) {
        float u = acc + __ldg(b2);
        out[i] = 1.f / (1.f + __expf(-u));
    }
}

// ---------------------------------------------------------------------------
// Launch
// ---------------------------------------------------------------------------
extern "C" void kernel_launch(void* const* d_in, const int* in_sizes, int n_in,
                              void* d_out, int out_size)
{
    const float* z   = (const float*)d_in[0];
    const int*   e32 = (const int*)d_in[1];
    const float* W1  = (const float*)d_in[2];
    const float* b1  = (const float*)d_in[3];
    const float* W2  = (const float*)d_in[4];
    const float* b2  = (const float*)d_in[5];
    float*       out = (float*)d_out;

    const int E = in_sizes[1] / 2;

    dim3 grid1((NNODES + 127) / 128, 2);
    node_proj_tc_kernel<<<grid1, 256>>>(z, W1, b1, e32);

    const int warps = (E + 3) / 4;                     // 4 edges per warp
    const int blocks2 = (warps * 32 + 255) / 256;
    edge_kernel<<<blocks2, 256>>>(e32, W2, b2, out, E);
}

// round 13
// speedup vs baseline: 2.1284x; 1.2576x over previous
#include <cuda_runtime.h>
#include <cuda_fp16.h>

// Problem constants
#define NNODES 50000
#define DIN    128
#define NH     128
#define PCOLS  256

// fp16 projection table: Pa = z@W1[:128]+b1 | Pb = z@W1[128:]. 25.6 MB, L2-resident.
__device__ __align__(16) __half g_Ph[(size_t)NNODES * PCOLS];
__device__ int g_e_is64;

// ---------------------------------------------------------------------------
// tf32 mma (m16n8k8). Inputs are raw f32 bits; HW truncates to tf32.
// ---------------------------------------------------------------------------
__device__ __forceinline__ void mma_tf32(float c[4], const unsigned a[4], const unsigned b[2]) {
    asm volatile(
        "mma.sync.aligned.m16n8k8.row.col.f32.tf32.tf32.f32 "
        "{%0,%1,%2,%3}, {%4,%5,%6,%7}, {%8,%9}, {%0,%1,%2,%3};\n"
        : "+f"(c[0]), "+f"(c[1]), "+f"(c[2]), "+f"(c[3])
        : "r"(a[0]), "r"(a[1]), "r"(a[2]), "r"(a[3]), "r"(b[0]), "r"(b[1]));
}

// ---------------------------------------------------------------------------
// Kernel 1: node projection GEMM on tensor cores (tf32, truncated inputs).
// Unchanged from R12 (passed, rel_err 2.2e-4).
// ---------------------------------------------------------------------------
#define AS_STRIDE 36
#define BS_STRIDE 132

__global__ __launch_bounds__(256, 2) void node_proj_tc_kernel(
    const float* __restrict__ z,
    const float* __restrict__ W1,
    const float* __restrict__ b1,
    const int*   __restrict__ e32)
{
    if (blockIdx.x == 0 && blockIdx.y == 0 && threadIdx.x < 32) {
        int l = threadIdx.x;
        int nz = (e32[2 * (2 * l) + 1] != 0) | (e32[2 * (2 * l + 1) + 1] != 0);
        unsigned bb = __ballot_sync(0xFFFFFFFFu, nz);
        if (l == 0) g_e_is64 = (bb == 0) ? 1 : 0;
    }

    __shared__ unsigned As[128 * AS_STRIDE];
    __shared__ unsigned Bs[32 * BS_STRIDE];

    const int m0   = blockIdx.x * 128;
    const int half = blockIdx.y;
    const float* Wbase = W1 + (size_t)half * NH * NH;

    const int t    = threadIdx.x;
    const int lane = t & 31;
    const int wid  = t >> 5;
    const int wm   = wid >> 2;
    const int wn   = wid & 3;
    const int g    = lane >> 2;
    const int c    = lane & 3;

    float acc[4][4][4];
#pragma unroll
    for (int ms = 0; ms < 4; ms++)
#pragma unroll
        for (int ns = 0; ns < 4; ns++)
#pragma unroll
            for (int r = 0; r < 4; r++) acc[ms][ns][r] = 0.f;

    const int arow  = t >> 1;
    const int acol0 = (t & 1) * 16;
    int a_row_g = m0 + arow;
    if (a_row_g >= NNODES) a_row_g = NNODES - 1;
    const int brow  = t >> 3;
    const int bcol0 = (t & 7) * 16;

#pragma unroll 1
    for (int k0 = 0; k0 < DIN; k0 += 32) {
        const float* zsrc = z + (size_t)a_row_g * DIN + k0 + acol0;
        unsigned* adst = &As[arow * AS_STRIDE + acol0];
#pragma unroll
        for (int j = 0; j < 4; j++) {
            uint4 v = *reinterpret_cast<const uint4*>(zsrc + 4 * j);
            adst[4*j+0] = v.x; adst[4*j+1] = v.y; adst[4*j+2] = v.z; adst[4*j+3] = v.w;
        }
        const float* wsrc = Wbase + (size_t)(k0 + brow) * NH + bcol0;
        unsigned* bdst = &Bs[brow * BS_STRIDE + bcol0];
#pragma unroll
        for (int j = 0; j < 4; j++) {
            uint4 v = *reinterpret_cast<const uint4*>(wsrc + 4 * j);
            bdst[4*j+0] = v.x; bdst[4*j+1] = v.y; bdst[4*j+2] = v.z; bdst[4*j+3] = v.w;
        }
        __syncthreads();

#pragma unroll
        for (int ko = 0; ko < 4; ko++) {
            const int kb = ko * 8;
            unsigned a[4][4], b[4][2];
#pragma unroll
            for (int ms = 0; ms < 4; ms++) {
                const int r0 = wm * 64 + ms * 16 + g;
                a[ms][0] = As[ r0      * AS_STRIDE + kb + c    ];
                a[ms][1] = As[(r0 + 8) * AS_STRIDE + kb + c    ];
                a[ms][2] = As[ r0      * AS_STRIDE + kb + c + 4];
                a[ms][3] = As[(r0 + 8) * AS_STRIDE + kb + c + 4];
            }
#pragma unroll
            for (int ns = 0; ns < 4; ns++) {
                const int col = wn * 32 + ns * 8 + g;
                b[ns][0] = Bs[(kb + c    ) * BS_STRIDE + col];
                b[ns][1] = Bs[(kb + c + 4) * BS_STRIDE + col];
            }
#pragma unroll
            for (int ms = 0; ms < 4; ms++)
#pragma unroll
                for (int ns = 0; ns < 4; ns++)
                    mma_tf32(acc[ms][ns], a[ms], b[ns]);
        }
        __syncthreads();
    }

#pragma unroll
    for (int ms = 0; ms < 4; ms++) {
        const int r0 = m0 + wm * 64 + ms * 16 + g;
#pragma unroll
        for (int ns = 0; ns < 4; ns++) {
            const int col = wn * 32 + ns * 8 + 2 * c;
            float bx = 0.f, by = 0.f;
            if (half == 0) { bx = __ldg(b1 + col); by = __ldg(b1 + col + 1); }
            if (r0 < NNODES) {
                __half2 h = __floats2half2_rn(acc[ms][ns][0] + bx, acc[ms][ns][1] + by);
                *reinterpret_cast<__half2*>(g_Ph + (size_t)r0 * PCOLS + half * NH + col) = h;
            }
            if (r0 + 8 < NNODES) {
                __half2 h = __floats2half2_rn(acc[ms][ns][2] + bx, acc[ms][ns][3] + by);
                *reinterpret_cast<__half2*>(g_Ph + (size_t)(r0 + 8) * PCOLS + half * NH + col) = h;
            }
        }
    }
}

// ---------------------------------------------------------------------------
// Kernel 2: PERSISTENT edge kernel. 4 edges per warp, 8 lanes per edge.
// W2 chunk (16 floats) and b2 live in registers across a grid-stride loop
// over edge-quads: kills the per-quad W2 reload (was 16 L1 wavefronts/quad,
// same as the table gathers themselves).
// ---------------------------------------------------------------------------
__global__ __launch_bounds__(256) void edge_kernel(
    const int* __restrict__ e32,
    const float* __restrict__ W2,
    const float* __restrict__ b2,
    float* __restrict__ out,
    int E)
{
    const int lane = threadIdx.x & 31;
    const int sub  = lane >> 3;      // edge slot within warp: 0..3
    const int j    = lane & 7;       // 16-value chunk: 0..7
    const int warp_global = (int)(blockIdx.x * (blockDim.x >> 5)) + (threadIdx.x >> 5);
    const int total_warps = (int)(gridDim.x * (blockDim.x >> 5));

    const int   is64 = g_e_is64;
    const float b2s  = __ldg(b2);

    // this lane's 16 w2 coefficients — loaded ONCE
    const float4* wp = reinterpret_cast<const float4*>(W2) + j * 4;
    const float4 w0 = __ldg(wp + 0);
    const float4 w1 = __ldg(wp + 1);
    const float4 w2c = __ldg(wp + 2);
    const float4 w3 = __ldg(wp + 3);

    const __half2 zero2 = __float2half2_rn(0.f);
    const int nquads = (E + 3) >> 2;

#pragma unroll 1
    for (int q = warp_global; q < nquads; q += total_warps) {
        int i = q * 4 + sub;
        const bool valid = (i < E);
        if (!valid) i = E - 1;

        int src, dst;
        if (is64) {
            src = __ldg(e32 + 2 * (size_t)i);
            dst = __ldg(e32 + 2 * ((size_t)E + i));
        } else {
            src = __ldg(e32 + i);
            dst = __ldg(e32 + E + i);
        }
        src = min(max(src, 0), NNODES - 1);
        dst = min(max(dst, 0), NNODES - 1);

        const uint4* pap = reinterpret_cast<const uint4*>(g_Ph + (size_t)src * PCOLS + j * 16);
        const uint4* pbp = reinterpret_cast<const uint4*>(g_Ph + (size_t)dst * PCOLS + NH + j * 16);
        uint4 pa0 = pap[0], pa1 = pap[1];
        uint4 pb0 = pbp[0], pb1 = pbp[1];

        const __half2* a2  = reinterpret_cast<const __half2*>(&pa0);
        const __half2* a3  = reinterpret_cast<const __half2*>(&pa1);
        const __half2* bv2 = reinterpret_cast<const __half2*>(&pb0);
        const __half2* bv3 = reinterpret_cast<const __half2*>(&pb1);

        __half2 h[8];
#pragma unroll
        for (int p = 0; p < 4; p++) h[p]     = __hmax2(__hadd2(a2[p], bv2[p]), zero2);
#pragma unroll
        for (int p = 0; p < 4; p++) h[4 + p] = __hmax2(__hadd2(a3[p], bv3[p]), zero2);

        float2 f0 = __half22float2(h[0]);
        float2 f1 = __half22float2(h[1]);
        float2 f2 = __half22float2(h[2]);
        float2 f3 = __half22float2(h[3]);
        float2 f4 = __half22float2(h[4]);
        float2 f5 = __half22float2(h[5]);
        float2 f6 = __half22float2(h[6]);
        float2 f7 = __half22float2(h[7]);

        float acc = 0.f;
        acc = fmaf(f0.x, w0.x, acc); acc = fmaf(f0.y, w0.y, acc);
        acc = fmaf(f1.x, w0.z, acc); acc = fmaf(f1.y, w0.w, acc);
        acc = fmaf(f2.x, w1.x, acc); acc = fmaf(f2.y, w1.y, acc);
        acc = fmaf(f3.x, w1.z, acc); acc = fmaf(f3.y, w1.w, acc);
        acc = fmaf(f4.x, w2c.x, acc); acc = fmaf(f4.y, w2c.y, acc);
        acc = fmaf(f5.x, w2c.z, acc); acc = fmaf(f5.y, w2c.w, acc);
        acc = fmaf(f6.x, w3.x, acc); acc = fmaf(f6.y, w3.y, acc);
        acc = fmaf(f7.x, w3.z, acc); acc = fmaf(f7.y, w3.w, acc);

        acc += __shfl_xor_sync(0xFFFFFFFFu, acc, 4, 8);
        acc += __shfl_xor_sync(0xFFFFFFFFu, acc, 2, 8);
        acc += __shfl_xor_sync(0xFFFFFFFFu, acc, 1, 8);

        if (j == 0 && valid) {
            float u = acc + b2s;
            out[i] = 1.f / (1.f + __expf(-u));
        }
    }
}

// ---------------------------------------------------------------------------
// Launch
// ---------------------------------------------------------------------------
extern "C" void kernel_launch(void* const* d_in, const int* in_sizes, int n_in,
                              void* d_out, int out_size)
{
    const float* z   = (const float*)d_in[0];
    const int*   e32 = (const int*)d_in[1];
    const float* W1  = (const float*)d_in[2];
    const float* b1  = (const float*)d_in[3];
    const float* W2  = (const float*)d_in[4];
    const float* b2  = (const float*)d_in[5];
    float*       out = (float*)d_out;

    const int E = in_sizes[1] / 2;

    dim3 grid1((NNODES + 127) / 128, 2);
    node_proj_tc_kernel<<<grid1, 256>>>(z, W1, b1, e32);

    // persistent: 8 CTAs per SM x 148 SMs
    const int nquads = (E + 3) / 4;
    int blocks2 = 148 * 8;
    const int max_blocks = (nquads * 32 + 255) / 256 * 4; // never more than work
    if (blocks2 > max_blocks) blocks2 = max_blocks;
    edge_kernel<<<blocks2, 256>>>(e32, W2, b2, out, E);
}

// round 14
// speedup vs baseline: 2.3651x; 1.1112x over previous
#include <cuda_runtime.h>
#include <cuda_fp16.h>

#define NNODES 50000
#define DIN    128
#define NH     128
#define PCOLS  256

// fp16 projection table: Pa = z@W1[:128]+b1 | Pb = z@W1[128:]. 25.6 MB, L2-resident.
__device__ __align__(16) __half g_Ph[(size_t)NNODES * PCOLS];
__device__ int g_e_is64;

// ---------------------------------------------------------------------------
// PTX helpers: ldmatrix + fp16 mma (m16n8k16, fp32 accum)
// ---------------------------------------------------------------------------
__device__ __forceinline__ unsigned smem_u32(const void* p) {
    return (unsigned)__cvta_generic_to_shared(p);
}
__device__ __forceinline__ void ldsm_x4(unsigned a[4], unsigned addr) {
    asm volatile("ldmatrix.sync.aligned.m8n8.x4.shared.b16 {%0,%1,%2,%3}, [%4];"
        : "=r"(a[0]), "=r"(a[1]), "=r"(a[2]), "=r"(a[3]) : "r"(addr));
}
__device__ __forceinline__ void ldsm_x2_trans(unsigned b[2], unsigned addr) {
    asm volatile("ldmatrix.sync.aligned.m8n8.x2.trans.shared.b16 {%0,%1}, [%2];"
        : "=r"(b[0]), "=r"(b[1]) : "r"(addr));
}
__device__ __forceinline__ void mma_f16(float c[4], const unsigned a[4], const unsigned b[2]) {
    asm volatile(
        "mma.sync.aligned.m16n8k16.row.col.f32.f16.f16.f32 "
        "{%0,%1,%2,%3}, {%4,%5,%6,%7}, {%8,%9}, {%0,%1,%2,%3};\n"
        : "+f"(c[0]), "+f"(c[1]), "+f"(c[2]), "+f"(c[3])
        : "r"(a[0]), "r"(a[1]), "r"(a[2]), "r"(a[3]), "r"(b[0]), "r"(b[1]));
}

// ---------------------------------------------------------------------------
// Kernel 1: node projection GEMM, fp16 HMMA + ldmatrix.
// C[128,128] = z_tile[128,128] @ W1_half[128,128]; fp32 accum; fp16 out.
// 256 threads = 8 warps; warp tile 64(m)x32(n); K staged 64 at a time.
// grid (ceil(M/128), 2). Block (0,0) warp 0 also detects e's dtype.
// ---------------------------------------------------------------------------
#define A_STRIDE 72     // halves per A row (64 + 8 pad) -> conflict-free LDSM
#define B_STRIDE 136    // halves per B k-row (128 + 8 pad)

__global__ __launch_bounds__(256, 2) void node_proj_tc_kernel(
    const float* __restrict__ z,
    const float* __restrict__ W1,
    const float* __restrict__ b1,
    const int*   __restrict__ e32)
{
    if (blockIdx.x == 0 && blockIdx.y == 0 && threadIdx.x < 32) {
        int l = threadIdx.x;
        int nz = (e32[2 * (2 * l) + 1] != 0) | (e32[2 * (2 * l + 1) + 1] != 0);
        unsigned bb = __ballot_sync(0xFFFFFFFFu, nz);
        if (l == 0) g_e_is64 = (bb == 0) ? 1 : 0;
    }

    __shared__ __align__(16) __half Ah[128 * A_STRIDE];   // 18 KB
    __shared__ __align__(16) __half Bh[64 * B_STRIDE];    // 17 KB

    const int m0   = blockIdx.x * 128;
    const int half = blockIdx.y;                 // 0 -> Pa(+b1), 1 -> Pb
    const float* Wbase = W1 + (size_t)half * NH * NH;

    const int t    = threadIdx.x;
    const int lane = t & 31;
    const int wid  = t >> 5;
    const int wm   = wid >> 2;                   // m block 64*wm
    const int wn   = wid & 3;                    // n block 32*wn

    float acc[4][4][4];
#pragma unroll
    for (int ms = 0; ms < 4; ms++)
#pragma unroll
        for (int ns = 0; ns < 4; ns++)
#pragma unroll
            for (int r = 0; r < 4; r++) acc[ms][ns][r] = 0.f;

    // staging maps
    const int a_row  = t >> 1;                   // 0..127
    const int a_c0   = (t & 1) * 32;             // 0 / 32
    int a_row_g = m0 + a_row;
    if (a_row_g >= NNODES) a_row_g = NNODES - 1; // clamp; stores guarded
    const int b_krow = t >> 2;                   // 0..63
    const int b_c0   = (t & 3) * 32;             // 0..96

    // ldmatrix lane geometry
    const int quad = lane >> 3, lrow = lane & 7, l15 = lane & 15;
    const int a_fr = (quad & 1) * 8 + lrow;      // frag row within 16
    const int a_fc = (quad >> 1) * 8;            // frag col half (0/8)

#pragma unroll 1
    for (int k0 = 0; k0 < DIN; k0 += 64) {
        // ---- stage A: 128 rows x 64 k, f32 -> fp16 ----
        {
            const float* src = z + (size_t)a_row_g * DIN + k0 + a_c0;
            __half* dst = Ah + a_row * A_STRIDE + a_c0;
#pragma unroll
            for (int jj = 0; jj < 4; jj++) {
                float4 v0 = *reinterpret_cast<const float4*>(src + 8 * jj);
                float4 v1 = *reinterpret_cast<const float4*>(src + 8 * jj + 4);
                __half2 h[4];
                h[0] = __floats2half2_rn(v0.x, v0.y);
                h[1] = __floats2half2_rn(v0.z, v0.w);
                h[2] = __floats2half2_rn(v1.x, v1.y);
                h[3] = __floats2half2_rn(v1.z, v1.w);
                *reinterpret_cast<uint4*>(dst + 8 * jj) = *reinterpret_cast<const uint4*>(h);
            }
        }
        // ---- stage B: 64 k-rows x 128 n ----
        {
            const float* src = Wbase + (size_t)(k0 + b_krow) * NH + b_c0;
            __half* dst = Bh + b_krow * B_STRIDE + b_c0;
#pragma unroll
            for (int jj = 0; jj < 4; jj++) {
                float4 v0 = *reinterpret_cast<const float4*>(src + 8 * jj);
                float4 v1 = *reinterpret_cast<const float4*>(src + 8 * jj + 4);
                __half2 h[4];
                h[0] = __floats2half2_rn(v0.x, v0.y);
                h[1] = __floats2half2_rn(v0.z, v0.w);
                h[2] = __floats2half2_rn(v1.x, v1.y);
                h[3] = __floats2half2_rn(v1.z, v1.w);
                *reinterpret_cast<uint4*>(dst + 8 * jj) = *reinterpret_cast<const uint4*>(h);
            }
        }
        __syncthreads();

#pragma unroll
        for (int kc = 0; kc < 4; kc++) {
            const int kb = kc * 16;
            unsigned a[4][4], b[4][2];
#pragma unroll
            for (int ms = 0; ms < 4; ms++) {
                const __half* p = Ah + (wm * 64 + ms * 16 + a_fr) * A_STRIDE + kb + a_fc;
                ldsm_x4(a[ms], smem_u32(p));
            }
#pragma unroll
            for (int ns = 0; ns < 4; ns++) {
                const __half* p = Bh + (kb + l15) * B_STRIDE + wn * 32 + ns * 8;
                ldsm_x2_trans(b[ns], smem_u32(p));
            }
#pragma unroll
            for (int ms = 0; ms < 4; ms++)
#pragma unroll
                for (int ns = 0; ns < 4; ns++)
                    mma_f16(acc[ms][ns], a[ms], b[ns]);
        }
        __syncthreads();
    }

    // ---- epilogue (same acc layout as before): +b1 on half 0, fp16 store ----
    const int g = lane >> 2, c = lane & 3;
#pragma unroll
    for (int ms = 0; ms < 4; ms++) {
        const int r0 = m0 + wm * 64 + ms * 16 + g;
#pragma unroll
        for (int ns = 0; ns < 4; ns++) {
            const int col = wn * 32 + ns * 8 + 2 * c;
            float bx = 0.f, by = 0.f;
            if (half == 0) { bx = __ldg(b1 + col); by = __ldg(b1 + col + 1); }
            if (r0 < NNODES) {
                __half2 h = __floats2half2_rn(acc[ms][ns][0] + bx, acc[ms][ns][1] + by);
                *reinterpret_cast<__half2*>(g_Ph + (size_t)r0 * PCOLS + half * NH + col) = h;
            }
            if (r0 + 8 < NNODES) {
                __half2 h = __floats2half2_rn(acc[ms][ns][2] + bx, acc[ms][ns][3] + by);
                *reinterpret_cast<__half2*>(g_Ph + (size_t)(r0 + 8) * PCOLS + half * NH + col) = h;
            }
        }
    }
}

// ---------------------------------------------------------------------------
// Kernel 2: persistent edge kernel, 4 edges/warp, 8 lanes/edge.
// Line-aligned gather: lane j reads CONTIGUOUS 16B chunks so each warp LDG
// touches exactly 1 L1 line per edge -> 16 wavefronts/quad (the floor).
// W2 (16 regs/lane) + b2 hoisted out of the grid-stride loop.
// ---------------------------------------------------------------------------
__global__ __launch_bounds__(256) void edge_kernel(
    const int* __restrict__ e32,
    const float* __restrict__ W2,
    const float* __restrict__ b2,
    float* __restrict__ out,
    int E)
{
    const int lane = threadIdx.x & 31;
    const int sub  = lane >> 3;       // edge slot 0..3
    const int j    = lane & 7;        // chunk 0..7
    const int warp_global = (int)(blockIdx.x * (blockDim.x >> 5)) + (threadIdx.x >> 5);
    const int total_warps = (int)(gridDim.x * (blockDim.x >> 5));

    const int   is64 = g_e_is64;
    const float b2s  = __ldg(b2);

    // lane j's w2 coefficients: halves [8j, 8j+8) and [64+8j, 64+8j+8)
    const float4* wpA = reinterpret_cast<const float4*>(W2 + j * 8);
    const float4* wpB = reinterpret_cast<const float4*>(W2 + 64 + j * 8);
    const float4 wA0 = __ldg(wpA), wA1 = __ldg(wpA + 1);
    const float4 wB0 = __ldg(wpB), wB1 = __ldg(wpB + 1);

    const __half2 zero2 = __float2half2_rn(0.f);
    const int nquads = (E + 3) >> 2;

#pragma unroll 1
    for (int q = warp_global; q < nquads; q += total_warps) {
        int i = q * 4 + sub;
        const bool valid = (i < E);
        if (!valid) i = E - 1;

        int src, dst;
        if (is64) {
            src = __ldg(e32 + 2 * (size_t)i);
            dst = __ldg(e32 + 2 * ((size_t)E + i));
        } else {
            src = __ldg(e32 + i);
            dst = __ldg(e32 + E + i);
        }
        src = min(max(src, 0), NNODES - 1);
        dst = min(max(dst, 0), NNODES - 1);

        const __half* pabase = g_Ph + (size_t)src * PCOLS;
        const __half* pbbase = g_Ph + (size_t)dst * PCOLS + NH;

        // contiguous 16B chunks: line 0 = halves [8j..8j+8), line 1 = +64
        uint4 pa0 = *reinterpret_cast<const uint4*>(pabase + j * 8);
        uint4 pa1 = *reinterpret_cast<const uint4*>(pabase + 64 + j * 8);
        uint4 pb0 = *reinterpret_cast<const uint4*>(pbbase + j * 8);
        uint4 pb1 = *reinterpret_cast<const uint4*>(pbbase + 64 + j * 8);

        const __half2* aA = reinterpret_cast<const __half2*>(&pa0);
        const __half2* aB = reinterpret_cast<const __half2*>(&pa1);
        const __half2* cA = reinterpret_cast<const __half2*>(&pb0);
        const __half2* cB = reinterpret_cast<const __half2*>(&pb1);

        __half2 h[8];
#pragma unroll
        for (int p = 0; p < 4; p++) h[p]     = __hmax2(__hadd2(aA[p], cA[p]), zero2);
#pragma unroll
        for (int p = 0; p < 4; p++) h[4 + p] = __hmax2(__hadd2(aB[p], cB[p]), zero2);

        float2 f0 = __half22float2(h[0]);
        float2 f1 = __half22float2(h[1]);
        float2 f2 = __half22float2(h[2]);
        float2 f3 = __half22float2(h[3]);
        float2 f4 = __half22float2(h[4]);
        float2 f5 = __half22float2(h[5]);
        float2 f6 = __half22float2(h[6]);
        float2 f7 = __half22float2(h[7]);

        float acc = 0.f;
        acc = fmaf(f0.x, wA0.x, acc); acc = fmaf(f0.y, wA0.y, acc);
        acc = fmaf(f1.x, wA0.z, acc); acc = fmaf(f1.y, wA0.w, acc);
        acc = fmaf(f2.x, wA1.x, acc); acc = fmaf(f2.y, wA1.y, acc);
        acc = fmaf(f3.x, wA1.z, acc); acc = fmaf(f3.y, wA1.w, acc);
        acc = fmaf(f4.x, wB0.x, acc); acc = fmaf(f4.y, wB0.y, acc);
        acc = fmaf(f5.x, wB0.z, acc); acc = fmaf(f5.y, wB0.w, acc);
        acc = fmaf(f6.x, wB1.x, acc); acc = fmaf(f6.y, wB1.y, acc);
        acc = fmaf(f7.x, wB1.z, acc); acc = fmaf(f7.y, wB1.w, acc);

        acc += __shfl_xor_sync(0xFFFFFFFFu, acc, 4, 8);
        acc += __shfl_xor_sync(0xFFFFFFFFu, acc, 2, 8);
        acc += __shfl_xor_sync(0xFFFFFFFFu, acc, 1, 8);

        if (j == 0 && valid) {
            float u = acc + b2s;
            out[i] = 1.f / (1.f + __expf(-u));
        }
    }
}

// ---------------------------------------------------------------------------
// Launch
// ---------------------------------------------------------------------------
extern "C" void kernel_launch(void* const* d_in, const int* in_sizes, int n_in,
                              void* d_out, int out_size)
{
    const float* z   = (const float*)d_in[0];
    const int*   e32 = (const int*)d_in[1];
    const float* W1  = (const float*)d_in[2];
    const float* b1  = (const float*)d_in[3];
    const float* W2  = (const float*)d_in[4];
    const float* b2  = (const float*)d_in[5];
    float*       out = (float*)d_out;

    const int E = in_sizes[1] / 2;

    dim3 grid1((NNODES + 127) / 128, 2);
    node_proj_tc_kernel<<<grid1, 256>>>(z, W1, b1, e32);

    const int nquads = (E + 3) / 4;
    int blocks2 = 148 * 8;
    const int max_blocks = (nquads * 32 + 255) / 256 * 4;
    if (blocks2 > max_blocks) blocks2 = max_blocks;
    edge_kernel<<<blocks2, 256>>>(e32, W2, b2, out, E);
}

// round 15
// speedup vs baseline: 2.6673x; 1.1278x over previous
#include <cuda_runtime.h>
#include <cuda_fp16.h>

#define NNODES 50000
#define DIN    128
#define NH     128
#define PCOLS  256

// fp16 projection table: Pa = z@W1[:128]+b1 | Pb. 25.6 MB, L2-resident.
__device__ __align__(16) __half g_Ph[(size_t)NNODES * PCOLS];
// fp16 pre-converted inputs
__device__ __align__(16) __half g_zh[(size_t)NNODES * DIN];      // 12.8 MB
__device__ __align__(16) __half g_W1hT[2 * NH * NH];             // [half][n][k]
__device__ int g_e_is64;

// ---------------------------------------------------------------------------
// PTX helpers
// ---------------------------------------------------------------------------
__device__ __forceinline__ unsigned smem_u32(const void* p) {
    return (unsigned)__cvta_generic_to_shared(p);
}
__device__ __forceinline__ void cp16(void* dst, const void* src) {
    asm volatile("cp.async.cg.shared.global [%0], [%1], 16;"
        :: "r"(smem_u32(dst)), "l"(src));
}
__device__ __forceinline__ void ldsm_x4(unsigned a[4], unsigned addr) {
    asm volatile("ldmatrix.sync.aligned.m8n8.x4.shared.b16 {%0,%1,%2,%3}, [%4];"
        : "=r"(a[0]), "=r"(a[1]), "=r"(a[2]), "=r"(a[3]) : "r"(addr));
}
__device__ __forceinline__ void mma_f16(float c[4], const unsigned a[4], const unsigned b[2]) {
    asm volatile(
        "mma.sync.aligned.m16n8k16.row.col.f32.f16.f16.f32 "
        "{%0,%1,%2,%3}, {%4,%5,%6,%7}, {%8,%9}, {%0,%1,%2,%3};\n"
        : "+f"(c[0]), "+f"(c[1]), "+f"(c[2]), "+f"(c[3])
        : "r"(a[0]), "r"(a[1]), "r"(a[2]), "r"(a[3]), "r"(b[0]), "r"(b[1]));
}

// ---------------------------------------------------------------------------
// Kernel A: one-time fp16 conversion. z -> g_zh; W1 -> g_W1hT (transposed to
// [half][n][k] so proj's B fragments load via non-trans ldmatrix).
// Block 0 warp 0 also detects e's dtype.
// ---------------------------------------------------------------------------
__global__ __launch_bounds__(256) void convert_kernel(
    const float* __restrict__ z,
    const float* __restrict__ W1,
    const int*   __restrict__ e32,
    int nzblocks)
{
    if (blockIdx.x == 0 && threadIdx.x < 32) {
        int l = threadIdx.x;
        int nz = (e32[2 * (2 * l) + 1] != 0) | (e32[2 * (2 * l + 1) + 1] != 0);
        unsigned bb = __ballot_sync(0xFFFFFFFFu, nz);
        if (l == 0) g_e_is64 = (bb == 0) ? 1 : 0;
    }

    if ((int)blockIdx.x < nzblocks) {
        size_t base = ((size_t)blockIdx.x * 256 + threadIdx.x) * 8;
        if (base + 8 <= (size_t)NNODES * DIN) {
            float4 v0 = *reinterpret_cast<const float4*>(z + base);
            float4 v1 = *reinterpret_cast<const float4*>(z + base + 4);
            __half2 h[4];
            h[0] = __floats2half2_rn(v0.x, v0.y);
            h[1] = __floats2half2_rn(v0.z, v0.w);
            h[2] = __floats2half2_rn(v1.x, v1.y);
            h[3] = __floats2half2_rn(v1.z, v1.w);
            *reinterpret_cast<uint4*>(g_zh + base) = *reinterpret_cast<const uint4*>(h);
        }
    } else {
        // W1 [256 rows k_in][128 cols n] -> g_W1hT[half][n][k] ; 32768 elems over 16 blocks
        int flat = ((int)blockIdx.x - nzblocks) * 2048 + (int)threadIdx.x * 8;
        int hh  = flat >> 14;
        int rem = flat & 16383;
        int n   = rem >> 7;
        int k0  = rem & 127;
        __half hv[8];
#pragma unroll
        for (int j = 0; j < 8; j++)
            hv[j] = __float2half_rn(W1[(size_t)(hh * NH + k0 + j) * NH + n]);
        *reinterpret_cast<uint4*>(g_W1hT + hh * NH * NH + n * NH + k0) =
            *reinterpret_cast<const uint4*>(hv);
    }
}

// ---------------------------------------------------------------------------
// Kernel 1: node projection GEMM, fp16 HMMA. Whole K=128 staged once per CTA
// via cp.async from pre-converted fp16 (no CVT/STS in the GEMM path).
// Block 128(m) x 128(n), 8 warps, warp tile 64x32. grid (ceil(M/128), 2).
// ---------------------------------------------------------------------------
#define PSTRIDE 136   // halves per smem row (128 + 8 pad): conflict-free ldsm

__global__ __launch_bounds__(256) void node_proj_tc_kernel(const float* __restrict__ b1)
{
    __shared__ __align__(16) __half Ah[128 * PSTRIDE];   // 34.8 KB
    __shared__ __align__(16) __half Bt[128 * PSTRIDE];   // 34.8 KB  (rows = n)

    const int m0   = blockIdx.x * 128;
    const int half = blockIdx.y;
    const int t    = threadIdx.x;
    const int lane = t & 31;
    const int wid  = t >> 5;
    const int wm   = wid >> 2;      // m block 64*wm
    const int wn   = wid & 3;       // n block 32*wn

    // ---- stage EVERYTHING with cp.async (16 x 16B per thread) ----
    {
        const int row = t >> 1;                 // 0..127
        const int c0  = (t & 1) * 64;           // halves: 0 / 64
        const int rowg = min(m0 + row, NNODES - 1);
        const __half* asrc = g_zh + (size_t)rowg * DIN + c0;
        __half* adst = Ah + row * PSTRIDE + c0;
        const __half* bsrc = g_W1hT + half * NH * NH + row * NH + c0;   // row = n
        __half* bdst = Bt + row * PSTRIDE + c0;
#pragma unroll
        for (int j = 0; j < 8; j++) cp16(adst + 8 * j, asrc + 8 * j);
#pragma unroll
        for (int j = 0; j < 8; j++) cp16(bdst + 8 * j, bsrc + 8 * j);
    }
    asm volatile("cp.async.commit_group;");
    asm volatile("cp.async.wait_group 0;");
    __syncthreads();

    float acc[4][4][4];
#pragma unroll
    for (int ms = 0; ms < 4; ms++)
#pragma unroll
        for (int ns = 0; ns < 4; ns++)
#pragma unroll
            for (int r = 0; r < 4; r++) acc[ms][ns][r] = 0.f;

    // ldmatrix lane geometry
    const int a_fr = lane & 15;            // A: row within 16
    const int a_fc = (lane >> 4) * 8;      // A: k col half
    const int bseg = lane >> 3;            // B: segment 0..3
    const int bidx = lane & 7;
    const int b_rowoff = (bseg >> 1) * 8 + bidx;   // n offset within 16
    const int b_coloff = (bseg & 1) * 8;           // k offset

#pragma unroll
    for (int kc = 0; kc < 8; kc++) {
        const int kb = kc * 16;
        unsigned a[4][4];
#pragma unroll
        for (int ms = 0; ms < 4; ms++) {
            const __half* p = Ah + (wm * 64 + ms * 16 + a_fr) * PSTRIDE + kb + a_fc;
            ldsm_x4(a[ms], smem_u32(p));
        }
        unsigned b[4][2];
#pragma unroll
        for (int nb = 0; nb < 2; nb++) {
            const int nbase = wn * 32 + nb * 16;
            unsigned r[4];
            const __half* p = Bt + (nbase + b_rowoff) * PSTRIDE + kb + b_coloff;
            ldsm_x4(r, smem_u32(p));
            b[2 * nb][0] = r[0]; b[2 * nb][1] = r[1];
            b[2 * nb + 1][0] = r[2]; b[2 * nb + 1][1] = r[3];
        }
#pragma unroll
        for (int ms = 0; ms < 4; ms++)
#pragma unroll
            for (int ns = 0; ns < 4; ns++)
                mma_f16(acc[ms][ns], a[ms], b[ns]);
    }

    // ---- epilogue: +b1 on half 0, fp16 store ----
    const int g = lane >> 2, c = lane & 3;
#pragma unroll
    for (int ms = 0; ms < 4; ms++) {
        const int r0 = m0 + wm * 64 + ms * 16 + g;
#pragma unroll
        for (int ns = 0; ns < 4; ns++) {
            const int col = wn * 32 + ns * 8 + 2 * c;
            float bx = 0.f, by = 0.f;
            if (half == 0) { bx = __ldg(b1 + col); by = __ldg(b1 + col + 1); }
            if (r0 < NNODES) {
                __half2 h = __floats2half2_rn(acc[ms][ns][0] + bx, acc[ms][ns][1] + by);
                *reinterpret_cast<__half2*>(g_Ph + (size_t)r0 * PCOLS + half * NH + col) = h;
            }
            if (r0 + 8 < NNODES) {
                __half2 h = __floats2half2_rn(acc[ms][ns][2] + bx, acc[ms][ns][3] + by);
                *reinterpret_cast<__half2*>(g_Ph + (size_t)(r0 + 8) * PCOLS + half * NH + col) = h;
            }
        }
    }
}

// ---------------------------------------------------------------------------
// Kernel 2: persistent edge kernel (unchanged from R14).
// 4 edges/warp, 8 lanes/edge, line-aligned 16B gathers, W2/b2 in registers.
// ---------------------------------------------------------------------------
__global__ __launch_bounds__(256) void edge_kernel(
    const int* __restrict__ e32,
    const float* __restrict__ W2,
    const float* __restrict__ b2,
    float* __restrict__ out,
    int E)
{
    const int lane = threadIdx.x & 31;
    const int sub  = lane >> 3;
    const int j    = lane & 7;
    const int warp_global = (int)(blockIdx.x * (blockDim.x >> 5)) + (threadIdx.x >> 5);
    const int total_warps = (int)(gridDim.x * (blockDim.x >> 5));

    const int   is64 = g_e_is64;
    const float b2s  = __ldg(b2);

    const float4* wpA = reinterpret_cast<const float4*>(W2 + j * 8);
    const float4* wpB = reinterpret_cast<const float4*>(W2 + 64 + j * 8);
    const float4 wA0 = __ldg(wpA), wA1 = __ldg(wpA + 1);
    const float4 wB0 = __ldg(wpB), wB1 = __ldg(wpB + 1);

    const __half2 zero2 = __float2half2_rn(0.f);
    const int nquads = (E + 3) >> 2;

#pragma unroll 1
    for (int q = warp_global; q < nquads; q += total_warps) {
        int i = q * 4 + sub;
        const bool valid = (i < E);
        if (!valid) i = E - 1;

        int src, dst;
        if (is64) {
            src = __ldg(e32 + 2 * (size_t)i);
            dst = __ldg(e32 + 2 * ((size_t)E + i));
        } else {
            src = __ldg(e32 + i);
            dst = __ldg(e32 + E + i);
        }
        src = min(max(src, 0), NNODES - 1);
        dst = min(max(dst, 0), NNODES - 1);

        const __half* pabase = g_Ph + (size_t)src * PCOLS;
        const __half* pbbase = g_Ph + (size_t)dst * PCOLS + NH;

        uint4 pa0 = *reinterpret_cast<const uint4*>(pabase + j * 8);
        uint4 pa1 = *reinterpret_cast<const uint4*>(pabase + 64 + j * 8);
        uint4 pb0 = *reinterpret_cast<const uint4*>(pbbase + j * 8);
        uint4 pb1 = *reinterpret_cast<const uint4*>(pbbase + 64 + j * 8);

        const __half2* aA = reinterpret_cast<const __half2*>(&pa0);
        const __half2* aB = reinterpret_cast<const __half2*>(&pa1);
        const __half2* cA = reinterpret_cast<const __half2*>(&pb0);
        const __half2* cB = reinterpret_cast<const __half2*>(&pb1);

        __half2 h[8];
#pragma unroll
        for (int p = 0; p < 4; p++) h[p]     = __hmax2(__hadd2(aA[p], cA[p]), zero2);
#pragma unroll
        for (int p = 0; p < 4; p++) h[4 + p] = __hmax2(__hadd2(aB[p], cB[p]), zero2);

        float2 f0 = __half22float2(h[0]);
        float2 f1 = __half22float2(h[1]);
        float2 f2 = __half22float2(h[2]);
        float2 f3 = __half22float2(h[3]);
        float2 f4 = __half22float2(h[4]);
        float2 f5 = __half22float2(h[5]);
        float2 f6 = __half22float2(h[6]);
        float2 f7 = __half22float2(h[7]);

        float acc = 0.f;
        acc = fmaf(f0.x, wA0.x, acc); acc = fmaf(f0.y, wA0.y, acc);
        acc = fmaf(f1.x, wA0.z, acc); acc = fmaf(f1.y, wA0.w, acc);
        acc = fmaf(f2.x, wA1.x, acc); acc = fmaf(f2.y, wA1.y, acc);
        acc = fmaf(f3.x, wA1.z, acc); acc = fmaf(f3.y, wA1.w, acc);
        acc = fmaf(f4.x, wB0.x, acc); acc = fmaf(f4.y, wB0.y, acc);
        acc = fmaf(f5.x, wB0.z, acc); acc = fmaf(f5.y, wB0.w, acc);
        acc = fmaf(f6.x, wB1.x, acc); acc = fmaf(f6.y, wB1.y, acc);
        acc = fmaf(f7.x, wB1.z, acc); acc = fmaf(f7.y, wB1.w, acc);

        acc += __shfl_xor_sync(0xFFFFFFFFu, acc, 4, 8);
        acc += __shfl_xor_sync(0xFFFFFFFFu, acc, 2, 8);
        acc += __shfl_xor_sync(0xFFFFFFFFu, acc, 1, 8);

        if (j == 0 && valid) {
            float u = acc + b2s;
            out[i] = 1.f / (1.f + __expf(-u));
        }
    }
}

// ---------------------------------------------------------------------------
// Launch
// ---------------------------------------------------------------------------
extern "C" void kernel_launch(void* const* d_in, const int* in_sizes, int n_in,
                              void* d_out, int out_size)
{
    const float* z   = (const float*)d_in[0];
    const int*   e32 = (const int*)d_in[1];
    const float* W1  = (const float*)d_in[2];
    const float* b1  = (const float*)d_in[3];
    const float* W2  = (const float*)d_in[4];
    const float* b2  = (const float*)d_in[5];
    float*       out = (float*)d_out;

    const int E = in_sizes[1] / 2;

    const int nzblocks = ((int)((size_t)NNODES * DIN) + 2047) / 2048;  // 3125
    convert_kernel<<<nzblocks + 16, 256>>>(z, W1, e32, nzblocks);

    dim3 grid1((NNODES + 127) / 128, 2);
    node_proj_tc_kernel<<<grid1, 256>>>(b1);

    const int nquads = (E + 3) / 4;
    int blocks2 = 148 * 8;
    const int max_blocks = (nquads * 32 + 255) / 256 * 4;
    if (blocks2 > max_blocks) blocks2 = max_blocks;
    edge_kernel<<<blocks2, 256>>>(e32, W2, b2, out, E);
}

// round 16
// speedup vs baseline: 2.8350x; 1.0629x over previous
#include <cuda_runtime.h>
#include <cuda_fp16.h>

#define NNODES 50000
#define DIN    128
#define NH     128
#define PCOLS  256

// fp16 projection table: Pa = z@W1[:128]+b1 | Pb. 25.6 MB, L2-resident.
__device__ __align__(16) __half g_Ph[(size_t)NNODES * PCOLS];
// fp16 pre-converted inputs
__device__ __align__(16) __half g_zh[(size_t)NNODES * DIN];      // 12.8 MB
__device__ __align__(16) __half g_W1hT[2 * NH * NH];             // [half][n][k]
__device__ int g_e_is64;

// ---------------------------------------------------------------------------
// PTX helpers
// ---------------------------------------------------------------------------
__device__ __forceinline__ unsigned smem_u32(const void* p) {
    return (unsigned)__cvta_generic_to_shared(p);
}
__device__ __forceinline__ void cp16(void* dst, const void* src) {
    asm volatile("cp.async.cg.shared.global [%0], [%1], 16;"
        :: "r"(smem_u32(dst)), "l"(src));
}
__device__ __forceinline__ void ldsm_x4(unsigned a[4], unsigned addr) {
    asm volatile("ldmatrix.sync.aligned.m8n8.x4.shared.b16 {%0,%1,%2,%3}, [%4];"
        : "=r"(a[0]), "=r"(a[1]), "=r"(a[2]), "=r"(a[3]) : "r"(addr));
}
__device__ __forceinline__ void mma_f16(float c[4], const unsigned a[4], const unsigned b[2]) {
    asm volatile(
        "mma.sync.aligned.m16n8k16.row.col.f32.f16.f16.f32 "
        "{%0,%1,%2,%3}, {%4,%5,%6,%7}, {%8,%9}, {%0,%1,%2,%3};\n"
        : "+f"(c[0]), "+f"(c[1]), "+f"(c[2]), "+f"(c[3])
        : "r"(a[0]), "r"(a[1]), "r"(a[2]), "r"(a[3]), "r"(b[0]), "r"(b[1]));
}

// ---------------------------------------------------------------------------
// Kernel A: one-time fp16 conversion with high MLP (32 floats / thread).
// z -> g_zh; W1 -> g_W1hT ([half][n][k]). Block 0 warp 0 detects e's dtype.
// ---------------------------------------------------------------------------
__global__ __launch_bounds__(256) void convert_kernel(
    const float* __restrict__ z,
    const float* __restrict__ W1,
    const int*   __restrict__ e32,
    int nzblocks)
{
    if (blockIdx.x == 0 && threadIdx.x < 32) {
        int l = threadIdx.x;
        int nz = (e32[2 * (2 * l) + 1] != 0) | (e32[2 * (2 * l + 1) + 1] != 0);
        unsigned bb = __ballot_sync(0xFFFFFFFFu, nz);
        if (l == 0) g_e_is64 = (bb == 0) ? 1 : 0;
    }

    if ((int)blockIdx.x < nzblocks) {
        // 32 floats per thread: 8 LDG.128 in flight -> latency hidden
        size_t base = ((size_t)blockIdx.x * 256 + threadIdx.x) * 32;
        const size_t total = (size_t)NNODES * DIN;
        float4 v[8];
        int nv = 0;
#pragma unroll
        for (int j = 0; j < 8; j++) {
            size_t o = base + 4 * j;
            if (o + 4 <= total) { v[j] = *reinterpret_cast<const float4*>(z + o); nv = j + 1; }
        }
#pragma unroll
        for (int j = 0; j < 8; j += 2) {
            if (j + 2 <= nv) {
                __half2 h[4];
                h[0] = __floats2half2_rn(v[j].x,   v[j].y);
                h[1] = __floats2half2_rn(v[j].z,   v[j].w);
                h[2] = __floats2half2_rn(v[j+1].x, v[j+1].y);
                h[3] = __floats2half2_rn(v[j+1].z, v[j+1].w);
                *reinterpret_cast<uint4*>(g_zh + base + 4 * j) = *reinterpret_cast<const uint4*>(h);
            }
        }
    } else {
        // W1 [256 k][128 n] -> g_W1hT[half][n][k]; 32768 elems over 16 blocks
        int flat = ((int)blockIdx.x - nzblocks) * 2048 + (int)threadIdx.x * 8;
        int hh  = flat >> 14;
        int rem = flat & 16383;
        int n   = rem >> 7;
        int k0  = rem & 127;
        __half hv[8];
#pragma unroll
        for (int j = 0; j < 8; j++)
            hv[j] = __float2half_rn(W1[(size_t)(hh * NH + k0 + j) * NH + n]);
        *reinterpret_cast<uint4*>(g_W1hT + hh * NH * NH + n * NH + k0) =
            *reinterpret_cast<const uint4*>(hv);
    }
}

// ---------------------------------------------------------------------------
// Kernel 1: node projection GEMM, fp16 HMMA, full-K cp.async staging.
// Block 128x128, 8 warps, warp tile 64x32. grid (ceil(M/128), 2).
// ---------------------------------------------------------------------------
#define PSTRIDE 136

__global__ __launch_bounds__(256) void node_proj_tc_kernel(const float* __restrict__ b1)
{
    __shared__ __align__(16) __half Ah[128 * PSTRIDE];
    __shared__ __align__(16) __half Bt[128 * PSTRIDE];

    const int m0   = blockIdx.x * 128;
    const int half = blockIdx.y;
    const int t    = threadIdx.x;
    const int lane = t & 31;
    const int wid  = t >> 5;
    const int wm   = wid >> 2;
    const int wn   = wid & 3;

    {
        const int row = t >> 1;
        const int c0  = (t & 1) * 64;
        const int rowg = min(m0 + row, NNODES - 1);
        const __half* asrc = g_zh + (size_t)rowg * DIN + c0;
        __half* adst = Ah + row * PSTRIDE + c0;
        const __half* bsrc = g_W1hT + half * NH * NH + row * NH + c0;
        __half* bdst = Bt + row * PSTRIDE + c0;
#pragma unroll
        for (int j = 0; j < 8; j++) cp16(adst + 8 * j, asrc + 8 * j);
#pragma unroll
        for (int j = 0; j < 8; j++) cp16(bdst + 8 * j, bsrc + 8 * j);
    }
    asm volatile("cp.async.commit_group;");
    asm volatile("cp.async.wait_group 0;");
    __syncthreads();

    float acc[4][4][4];
#pragma unroll
    for (int ms = 0; ms < 4; ms++)
#pragma unroll
        for (int ns = 0; ns < 4; ns++)
#pragma unroll
            for (int r = 0; r < 4; r++) acc[ms][ns][r] = 0.f;

    const int a_fr = lane & 15;
    const int a_fc = (lane >> 4) * 8;
    const int bseg = lane >> 3;
    const int bidx = lane & 7;
    const int b_rowoff = (bseg >> 1) * 8 + bidx;
    const int b_coloff = (bseg & 1) * 8;

#pragma unroll
    for (int kc = 0; kc < 8; kc++) {
        const int kb = kc * 16;
        unsigned a[4][4];
#pragma unroll
        for (int ms = 0; ms < 4; ms++) {
            const __half* p = Ah + (wm * 64 + ms * 16 + a_fr) * PSTRIDE + kb + a_fc;
            ldsm_x4(a[ms], smem_u32(p));
        }
        unsigned b[4][2];
#pragma unroll
        for (int nb = 0; nb < 2; nb++) {
            const int nbase = wn * 32 + nb * 16;
            unsigned r[4];
            const __half* p = Bt + (nbase + b_rowoff) * PSTRIDE + kb + b_coloff;
            ldsm_x4(r, smem_u32(p));
            b[2 * nb][0] = r[0]; b[2 * nb][1] = r[1];
            b[2 * nb + 1][0] = r[2]; b[2 * nb + 1][1] = r[3];
        }
#pragma unroll
        for (int ms = 0; ms < 4; ms++)
#pragma unroll
            for (int ns = 0; ns < 4; ns++)
                mma_f16(acc[ms][ns], a[ms], b[ns]);
    }

    // epilogue: bias hoisted (depends only on ns), fp16 store
    const int g = lane >> 2, c = lane & 3;
    float bx[4], by[4];
#pragma unroll
    for (int ns = 0; ns < 4; ns++) {
        const int col = wn * 32 + ns * 8 + 2 * c;
        bx[ns] = (half == 0) ? __ldg(b1 + col)     : 0.f;
        by[ns] = (half == 0) ? __ldg(b1 + col + 1) : 0.f;
    }
#pragma unroll
    for (int ms = 0; ms < 4; ms++) {
        const int r0 = m0 + wm * 64 + ms * 16 + g;
#pragma unroll
        for (int ns = 0; ns < 4; ns++) {
            const int col = wn * 32 + ns * 8 + 2 * c;
            if (r0 < NNODES) {
                __half2 h = __floats2half2_rn(acc[ms][ns][0] + bx[ns], acc[ms][ns][1] + by[ns]);
                *reinterpret_cast<__half2*>(g_Ph + (size_t)r0 * PCOLS + half * NH + col) = h;
            }
            if (r0 + 8 < NNODES) {
                __half2 h = __floats2half2_rn(acc[ms][ns][2] + bx[ns], acc[ms][ns][3] + by[ns]);
                *reinterpret_cast<__half2*>(g_Ph + (size_t)(r0 + 8) * PCOLS + half * NH + col) = h;
            }
        }
    }
}

// ---------------------------------------------------------------------------
// Kernel 2: persistent edge kernel, 4 edges/warp, 8 lanes/edge.
// NEW: dot product via half2 HFMA2 chain (w2 pre-converted to half2 in
// registers) -> ~28 instrs/lane vs ~44 with the f32 path.
// ---------------------------------------------------------------------------
__global__ __launch_bounds__(256) void edge_kernel(
    const int* __restrict__ e32,
    const float* __restrict__ W2,
    const float* __restrict__ b2,
    float* __restrict__ out,
    int E)
{
    const int lane = threadIdx.x & 31;
    const int sub  = lane >> 3;
    const int j    = lane & 7;
    const int warp_global = (int)(blockIdx.x * (blockDim.x >> 5)) + (threadIdx.x >> 5);
    const int total_warps = (int)(gridDim.x * (blockDim.x >> 5));

    const int   is64 = g_e_is64;
    const float b2s  = __ldg(b2);

    // lane j's 16 w2 coefficients, pre-converted to 8 half2
    __half2 w2h[8];
    {
        const float4* wpA = reinterpret_cast<const float4*>(W2 + j * 8);
        const float4* wpB = reinterpret_cast<const float4*>(W2 + 64 + j * 8);
        float4 wA0 = __ldg(wpA), wA1 = __ldg(wpA + 1);
        float4 wB0 = __ldg(wpB), wB1 = __ldg(wpB + 1);
        w2h[0] = __floats2half2_rn(wA0.x, wA0.y);
        w2h[1] = __floats2half2_rn(wA0.z, wA0.w);
        w2h[2] = __floats2half2_rn(wA1.x, wA1.y);
        w2h[3] = __floats2half2_rn(wA1.z, wA1.w);
        w2h[4] = __floats2half2_rn(wB0.x, wB0.y);
        w2h[5] = __floats2half2_rn(wB0.z, wB0.w);
        w2h[6] = __floats2half2_rn(wB1.x, wB1.y);
        w2h[7] = __floats2half2_rn(wB1.z, wB1.w);
    }

    const __half2 zero2 = __float2half2_rn(0.f);
    const int nquads = (E + 3) >> 2;

#pragma unroll 1
    for (int q = warp_global; q < nquads; q += total_warps) {
        int i = q * 4 + sub;
        const bool valid = (i < E);
        if (!valid) i = E - 1;

        int src, dst;
        if (is64) {
            src = __ldg(e32 + 2 * (size_t)i);
            dst = __ldg(e32 + 2 * ((size_t)E + i));
        } else {
            src = __ldg(e32 + i);
            dst = __ldg(e32 + E + i);
        }
        src = min(max(src, 0), NNODES - 1);
        dst = min(max(dst, 0), NNODES - 1);

        const __half* pabase = g_Ph + (size_t)src * PCOLS;
        const __half* pbbase = g_Ph + (size_t)dst * PCOLS + NH;

        uint4 pa0 = *reinterpret_cast<const uint4*>(pabase + j * 8);
        uint4 pa1 = *reinterpret_cast<const uint4*>(pabase + 64 + j * 8);
        uint4 pb0 = *reinterpret_cast<const uint4*>(pbbase + j * 8);
        uint4 pb1 = *reinterpret_cast<const uint4*>(pbbase + 64 + j * 8);

        const __half2* aA = reinterpret_cast<const __half2*>(&pa0);
        const __half2* aB = reinterpret_cast<const __half2*>(&pa1);
        const __half2* cA = reinterpret_cast<const __half2*>(&pb0);
        const __half2* cB = reinterpret_cast<const __half2*>(&pb1);

        // relu(add) then fp16 FMA accumulate (two chains to shorten deps)
        __half2 acc2a = zero2, acc2b = zero2;
#pragma unroll
        for (int p = 0; p < 4; p++) {
            __half2 h = __hmax2(__hadd2(aA[p], cA[p]), zero2);
            acc2a = __hfma2(h, w2h[p], acc2a);
        }
#pragma unroll
        for (int p = 0; p < 4; p++) {
            __half2 h = __hmax2(__hadd2(aB[p], cB[p]), zero2);
            acc2b = __hfma2(h, w2h[4 + p], acc2b);
        }
        float2 fa = __half22float2(acc2a);
        float2 fb = __half22float2(acc2b);
        float acc = (fa.x + fa.y) + (fb.x + fb.y);

        acc += __shfl_xor_sync(0xFFFFFFFFu, acc, 4, 8);
        acc += __shfl_xor_sync(0xFFFFFFFFu, acc, 2, 8);
        acc += __shfl_xor_sync(0xFFFFFFFFu, acc, 1, 8);

        if (j == 0 && valid) {
            float u = acc + b2s;
            out[i] = 1.f / (1.f + __expf(-u));
        }
    }
}

// ---------------------------------------------------------------------------
// Launch
// ---------------------------------------------------------------------------
extern "C" void kernel_launch(void* const* d_in, const int* in_sizes, int n_in,
                              void* d_out, int out_size)
{
    const float* z   = (const float*)d_in[0];
    const int*   e32 = (const int*)d_in[1];
    const float* W1  = (const float*)d_in[2];
    const float* b1  = (const float*)d_in[3];
    const float* W2  = (const float*)d_in[4];
    const float* b2  = (const float*)d_in[5];
    float*       out = (float*)d_out;

    const int E = in_sizes[1] / 2;

    const int nzblocks = ((int)((size_t)NNODES * DIN) + (256 * 32 - 1)) / (256 * 32);  // 782
    convert_kernel<<<nzblocks + 16, 256>>>(z, W1, e32, nzblocks);

    dim3 grid1((NNODES + 127) / 128, 2);
    node_proj_tc_kernel<<<grid1, 256>>>(b1);

    const int nquads = (E + 3) / 4;
    int blocks2 = 148 * 8;
    const int max_blocks = (nquads * 32 + 255) / 256 * 4;
    if (blocks2 > max_blocks) blocks2 = max_blocks;
    edge_kernel<<<blocks2, 256>>>(e32, W2, b2, out, E);
}

// round 17
// speedup vs baseline: 2.8977x; 1.0221x over previous
#include <cuda_runtime.h>
#include <cuda_fp16.h>

#define NNODES 50000
#define DIN    128
#define NH     128
#define PCOLS  256

// fp16 projection table: Pa = z@W1[:128]+b1 | Pb. 25.6 MB, L2-resident.
__device__ __align__(16) __half g_Ph[(size_t)NNODES * PCOLS];
// fp16 pre-converted inputs
__device__ __align__(16) __half g_zh[(size_t)NNODES * DIN];      // 12.8 MB
__device__ __align__(16) __half g_W1hT[2 * NH * NH];             // [half][n][k]
__device__ int g_e_is64;

// ---------------------------------------------------------------------------
// PTX helpers
// ---------------------------------------------------------------------------
__device__ __forceinline__ unsigned smem_u32(const void* p) {
    return (unsigned)__cvta_generic_to_shared(p);
}
__device__ __forceinline__ void cp16(void* dst, const void* src) {
    asm volatile("cp.async.cg.shared.global [%0], [%1], 16;"
        :: "r"(smem_u32(dst)), "l"(src));
}
__device__ __forceinline__ void ldsm_x4(unsigned a[4], unsigned addr) {
    asm volatile("ldmatrix.sync.aligned.m8n8.x4.shared.b16 {%0,%1,%2,%3}, [%4];"
        : "=r"(a[0]), "=r"(a[1]), "=r"(a[2]), "=r"(a[3]) : "r"(addr));
}
__device__ __forceinline__ void mma_f16(float c[4], const unsigned a[4], const unsigned b[2]) {
    asm volatile(
        "mma.sync.aligned.m16n8k16.row.col.f32.f16.f16.f32 "
        "{%0,%1,%2,%3}, {%4,%5,%6,%7}, {%8,%9}, {%0,%1,%2,%3};\n"
        : "+f"(c[0]), "+f"(c[1]), "+f"(c[2]), "+f"(c[3])
        : "r"(a[0]), "r"(a[1]), "r"(a[2]), "r"(a[3]), "r"(b[0]), "r"(b[1]));
}

// ---------------------------------------------------------------------------
// Kernel A: one-time fp16 conversion. 16 floats / thread (MLP=4), no staging
// array, no tail logic (6.4M elems = exact multiple of 256*16).
// Block 0 warp 0 detects e's dtype.
// ---------------------------------------------------------------------------
__global__ __launch_bounds__(256) void convert_kernel(
    const float* __restrict__ z,
    const float* __restrict__ W1,
    const int*   __restrict__ e32,
    int nzblocks)
{
    if (blockIdx.x == 0 && threadIdx.x < 32) {
        int l = threadIdx.x;
        int nz = (e32[2 * (2 * l) + 1] != 0) | (e32[2 * (2 * l + 1) + 1] != 0);
        unsigned bb = __ballot_sync(0xFFFFFFFFu, nz);
        if (l == 0) g_e_is64 = (bb == 0) ? 1 : 0;
    }

    if ((int)blockIdx.x < nzblocks) {
        // 16 floats per thread: 4 independent LDG.128 in flight
        size_t base = ((size_t)blockIdx.x * 256 + threadIdx.x) * 16;
        float4 v0 = *reinterpret_cast<const float4*>(z + base);
        float4 v1 = *reinterpret_cast<const float4*>(z + base + 4);
        float4 v2 = *reinterpret_cast<const float4*>(z + base + 8);
        float4 v3 = *reinterpret_cast<const float4*>(z + base + 12);
        __half2 h[4];
        h[0] = __floats2half2_rn(v0.x, v0.y);
        h[1] = __floats2half2_rn(v0.z, v0.w);
        h[2] = __floats2half2_rn(v1.x, v1.y);
        h[3] = __floats2half2_rn(v1.z, v1.w);
        *reinterpret_cast<uint4*>(g_zh + base) = *reinterpret_cast<const uint4*>(h);
        h[0] = __floats2half2_rn(v2.x, v2.y);
        h[1] = __floats2half2_rn(v2.z, v2.w);
        h[2] = __floats2half2_rn(v3.x, v3.y);
        h[3] = __floats2half2_rn(v3.z, v3.w);
        *reinterpret_cast<uint4*>(g_zh + base + 8) = *reinterpret_cast<const uint4*>(h);
    } else {
        // W1 [256 k][128 n] -> g_W1hT[half][n][k]; 32768 elems over 16 blocks
        int flat = ((int)blockIdx.x - nzblocks) * 2048 + (int)threadIdx.x * 8;
        int hh  = flat >> 14;
        int rem = flat & 16383;
        int n   = rem >> 7;
        int k0  = rem & 127;
        __half hv[8];
#pragma unroll
        for (int j = 0; j < 8; j++)
            hv[j] = __float2half_rn(W1[(size_t)(hh * NH + k0 + j) * NH + n]);
        *reinterpret_cast<uint4*>(g_W1hT + hh * NH * NH + n * NH + k0) =
            *reinterpret_cast<const uint4*>(hv);
    }
}

// ---------------------------------------------------------------------------
// Kernel 1: node projection GEMM, fp16 HMMA, full-K cp.async staging.
// Unchanged from R16.
// ---------------------------------------------------------------------------
#define PSTRIDE 136

__global__ __launch_bounds__(256) void node_proj_tc_kernel(const float* __restrict__ b1)
{
    __shared__ __align__(16) __half Ah[128 * PSTRIDE];
    __shared__ __align__(16) __half Bt[128 * PSTRIDE];

    const int m0   = blockIdx.x * 128;
    const int half = blockIdx.y;
    const int t    = threadIdx.x;
    const int lane = t & 31;
    const int wid  = t >> 5;
    const int wm   = wid >> 2;
    const int wn   = wid & 3;

    {
        const int row = t >> 1;
        const int c0  = (t & 1) * 64;
        const int rowg = min(m0 + row, NNODES - 1);
        const __half* asrc = g_zh + (size_t)rowg * DIN + c0;
        __half* adst = Ah + row * PSTRIDE + c0;
        const __half* bsrc = g_W1hT + half * NH * NH + row * NH + c0;
        __half* bdst = Bt + row * PSTRIDE + c0;
#pragma unroll
        for (int j = 0; j < 8; j++) cp16(adst + 8 * j, asrc + 8 * j);
#pragma unroll
        for (int j = 0; j < 8; j++) cp16(bdst + 8 * j, bsrc + 8 * j);
    }
    asm volatile("cp.async.commit_group;");
    asm volatile("cp.async.wait_group 0;");
    __syncthreads();

    float acc[4][4][4];
#pragma unroll
    for (int ms = 0; ms < 4; ms++)
#pragma unroll
        for (int ns = 0; ns < 4; ns++)
#pragma unroll
            for (int r = 0; r < 4; r++) acc[ms][ns][r] = 0.f;

    const int a_fr = lane & 15;
    const int a_fc = (lane >> 4) * 8;
    const int bseg = lane >> 3;
    const int bidx = lane & 7;
    const int b_rowoff = (bseg >> 1) * 8 + bidx;
    const int b_coloff = (bseg & 1) * 8;

#pragma unroll
    for (int kc = 0; kc < 8; kc++) {
        const int kb = kc * 16;
        unsigned a[4][4];
#pragma unroll
        for (int ms = 0; ms < 4; ms++) {
            const __half* p = Ah + (wm * 64 + ms * 16 + a_fr) * PSTRIDE + kb + a_fc;
            ldsm_x4(a[ms], smem_u32(p));
        }
        unsigned b[4][2];
#pragma unroll
        for (int nb = 0; nb < 2; nb++) {
            const int nbase = wn * 32 + nb * 16;
            unsigned r[4];
            const __half* p = Bt + (nbase + b_rowoff) * PSTRIDE + kb + b_coloff;
            ldsm_x4(r, smem_u32(p));
            b[2 * nb][0] = r[0]; b[2 * nb][1] = r[1];
            b[2 * nb + 1][0] = r[2]; b[2 * nb + 1][1] = r[3];
        }
#pragma unroll
        for (int ms = 0; ms < 4; ms++)
#pragma unroll
            for (int ns = 0; ns < 4; ns++)
                mma_f16(acc[ms][ns], a[ms], b[ns]);
    }

    const int g = lane >> 2, c = lane & 3;
    float bx[4], by[4];
#pragma unroll
    for (int ns = 0; ns < 4; ns++) {
        const int col = wn * 32 + ns * 8 + 2 * c;
        bx[ns] = (half == 0) ? __ldg(b1 + col)     : 0.f;
        by[ns] = (half == 0) ? __ldg(b1 + col + 1) : 0.f;
    }
#pragma unroll
    for (int ms = 0; ms < 4; ms++) {
        const int r0 = m0 + wm * 64 + ms * 16 + g;
#pragma unroll
        for (int ns = 0; ns < 4; ns++) {
            const int col = wn * 32 + ns * 8 + 2 * c;
            if (r0 < NNODES) {
                __half2 h = __floats2half2_rn(acc[ms][ns][0] + bx[ns], acc[ms][ns][1] + by[ns]);
                *reinterpret_cast<__half2*>(g_Ph + (size_t)r0 * PCOLS + half * NH + col) = h;
            }
            if (r0 + 8 < NNODES) {
                __half2 h = __floats2half2_rn(acc[ms][ns][2] + bx[ns], acc[ms][ns][3] + by[ns]);
                *reinterpret_cast<__half2*>(g_Ph + (size_t)(r0 + 8) * PCOLS + half * NH + col) = h;
            }
        }
    }
}

// ---------------------------------------------------------------------------
// Kernel 2: persistent edge kernel, 4 edges/warp, 8 lanes/edge, HFMA2 dot.
// NEW: next-iteration index prefetch to pull the index L2 round-trip off the
// critical path of each loop iteration.
// ---------------------------------------------------------------------------
__global__ __launch_bounds__(256) void edge_kernel(
    const int* __restrict__ e32,
    const float* __restrict__ W2,
    const float* __restrict__ b2,
    float* __restrict__ out,
    int E)
{
    const int lane = threadIdx.x & 31;
    const int sub  = lane >> 3;
    const int j    = lane & 7;
    const int warp_global = (int)(blockIdx.x * (blockDim.x >> 5)) + (threadIdx.x >> 5);
    const int total_warps = (int)(gridDim.x * (blockDim.x >> 5));

    const int   is64 = g_e_is64;
    const float b2s  = __ldg(b2);

    __half2 w2h[8];
    {
        const float4* wpA = reinterpret_cast<const float4*>(W2 + j * 8);
        const float4* wpB = reinterpret_cast<const float4*>(W2 + 64 + j * 8);
        float4 wA0 = __ldg(wpA), wA1 = __ldg(wpA + 1);
        float4 wB0 = __ldg(wpB), wB1 = __ldg(wpB + 1);
        w2h[0] = __floats2half2_rn(wA0.x, wA0.y);
        w2h[1] = __floats2half2_rn(wA0.z, wA0.w);
        w2h[2] = __floats2half2_rn(wA1.x, wA1.y);
        w2h[3] = __floats2half2_rn(wA1.z, wA1.w);
        w2h[4] = __floats2half2_rn(wB0.x, wB0.y);
        w2h[5] = __floats2half2_rn(wB0.z, wB0.w);
        w2h[6] = __floats2half2_rn(wB1.x, wB1.y);
        w2h[7] = __floats2half2_rn(wB1.z, wB1.w);
    }

    const __half2 zero2 = __float2half2_rn(0.f);
    const int nquads = (E + 3) >> 2;

    // index loader for quad q (this lane's edge slot)
    auto load_idx = [&](int q, int& s, int& d) {
        int i = min(q * 4 + sub, E - 1);
        if (is64) {
            s = __ldg(e32 + 2 * (size_t)i);
            d = __ldg(e32 + 2 * ((size_t)E + i));
        } else {
            s = __ldg(e32 + i);
            d = __ldg(e32 + E + i);
        }
        s = min(max(s, 0), NNODES - 1);
        d = min(max(d, 0), NNODES - 1);
    };

    int q = warp_global;
    int src, dst;
    if (q < nquads) load_idx(q, src, dst);

#pragma unroll 1
    for (; q < nquads; q += total_warps) {
        const int i = q * 4 + sub;
        const bool valid = (i < E);
        const int iw = valid ? i : (E - 1);

        const __half* pabase = g_Ph + (size_t)src * PCOLS;
        const __half* pbbase = g_Ph + (size_t)dst * PCOLS + NH;

        uint4 pa0 = *reinterpret_cast<const uint4*>(pabase + j * 8);
        uint4 pa1 = *reinterpret_cast<const uint4*>(pabase + 64 + j * 8);
        uint4 pb0 = *reinterpret_cast<const uint4*>(pbbase + j * 8);
        uint4 pb1 = *reinterpret_cast<const uint4*>(pbbase + 64 + j * 8);

        // prefetch next iteration's indices while gathers are in flight
        int nq = q + total_warps;
        if (nq < nquads) load_idx(nq, src, dst);

        const __half2* aA = reinterpret_cast<const __half2*>(&pa0);
        const __half2* aB = reinterpret_cast<const __half2*>(&pa1);
        const __half2* cA = reinterpret_cast<const __half2*>(&pb0);
        const __half2* cB = reinterpret_cast<const __half2*>(&pb1);

        __half2 acc2a = zero2, acc2b = zero2;
#pragma unroll
        for (int p = 0; p < 4; p++) {
            __half2 h = __hmax2(__hadd2(aA[p], cA[p]), zero2);
            acc2a = __hfma2(h, w2h[p], acc2a);
        }
#pragma unroll
        for (int p = 0; p < 4; p++) {
            __half2 h = __hmax2(__hadd2(aB[p], cB[p]), zero2);
            acc2b = __hfma2(h, w2h[4 + p], acc2b);
        }
        float2 fa = __half22float2(acc2a);
        float2 fb = __half22float2(acc2b);
        float acc = (fa.x + fa.y) + (fb.x + fb.y);

        acc += __shfl_xor_sync(0xFFFFFFFFu, acc, 4, 8);
        acc += __shfl_xor_sync(0xFFFFFFFFu, acc, 2, 8);
        acc += __shfl_xor_sync(0xFFFFFFFFu, acc, 1, 8);

        if (j == 0 && valid) {
            float u = acc + b2s;
            out[iw] = 1.f / (1.f + __expf(-u));
        }
    }
}

// ---------------------------------------------------------------------------
// Launch
// ---------------------------------------------------------------------------
extern "C" void kernel_launch(void* const* d_in, const int* in_sizes, int n_in,
                              void* d_out, int out_size)
{
    const float* z   = (const float*)d_in[0];
    const int*   e32 = (const int*)d_in[1];
    const float* W1  = (const float*)d_in[2];
    const float* b1  = (const float*)d_in[3];
    const float* W2  = (const float*)d_in[4];
    const float* b2  = (const float*)d_in[5];
    float*       out = (float*)d_out;

    const int E = in_sizes[1] / 2;

    const int nzblocks = ((int)((size_t)NNODES * DIN)) / (256 * 16);   // 1562.5 -> need ceil
    const int nzb = ((int)((size_t)NNODES * DIN) + (256 * 16 - 1)) / (256 * 16);  // 1563
    (void)nzblocks;
    convert_kernel<<<nzb + 16, 256>>>(z, W1, e32, nzb);

    dim3 grid1((NNODES + 127) / 128, 2);
    node_proj_tc_kernel<<<grid1, 256>>>(b1);

    const int nquads = (E + 3) / 4;
    int blocks2 = 148 * 8;
    const int max_blocks = (nquads * 32 + 255) / 256 * 4;
    if (blocks2 > max_blocks) blocks2 = max_blocks;
    edge_kernel<<<blocks2, 256>>>(e32, W2, b2, out, E);
}